// round 14
// baseline (speedup 1.0000x reference)
#include <cuda_runtime.h>
#include <cuda_bf16.h>
#include <math.h>
#include <stdint.h>

#define B_   8
#define T_   512
#define DM_  1024
#define H_   16
#define DH_  64
#define P_   3584
#define BT_  (B_*T_)       // 4096
#define BHTD_ (B_*H_*T_*DH_)   // 4194304
#define BHPD_ (B_*H_*P_*DH_)   // 29360128
#define QSC_ 0.18033688011112042f   // 0.125 * log2(e): scores in log2 units

// ---------------- scratch (device globals; zero-initialized at load) ----------------
__device__ __nv_bfloat16 g_x_hi[BT_*DM_];
__device__ __nv_bfloat16 g_x_lo[BT_*DM_];
__device__ __nv_bfloat16 g_at_hi[BT_*DM_];
__device__ __nv_bfloat16 g_at_lo[BT_*DM_];
__device__ __nv_bfloat16 g_wt_hi[4*DM_*DM_];
__device__ __nv_bfloat16 g_wt_lo[4*DM_*DM_];
__device__ __nv_bfloat16 g_qh [BHTD_+64*DH_];
__device__ __nv_bfloat16 g_ql [BHTD_+64*DH_];
__device__ __nv_bfloat16 g_knh[BHTD_+64*DH_];
__device__ __nv_bfloat16 g_knl[BHTD_+64*DH_];
__device__ __nv_bfloat16 g_vnh[BHTD_+64*DH_];
__device__ __nv_bfloat16 g_vnl[BHTD_+64*DH_];
__device__ __nv_bfloat16 g_pkh[BHPD_];
__device__ __nv_bfloat16 g_pkl[BHPD_];
__device__ __nv_bfloat16 g_pvh[BHPD_];
__device__ __nv_bfloat16 g_pvl[BHPD_];

// ---------------- helpers ----------------
__device__ __forceinline__ uint32_t smem_u32(const void* p) {
    uint32_t a;
    asm("{ .reg .u64 t; cvta.to.shared.u64 t, %1; cvt.u32.u64 %0, t; }" : "=r"(a) : "l"(p));
    return a;
}
__device__ __forceinline__ void ldm_x4(uint32_t* r, uint32_t addr) {
    asm volatile("ldmatrix.sync.aligned.m8n8.x4.shared.b16 {%0,%1,%2,%3}, [%4];"
        : "=r"(r[0]), "=r"(r[1]), "=r"(r[2]), "=r"(r[3]) : "r"(addr));
}
__device__ __forceinline__ void ldm_x2(uint32_t* r, uint32_t addr) {
    asm volatile("ldmatrix.sync.aligned.m8n8.x2.shared.b16 {%0,%1}, [%2];"
        : "=r"(r[0]), "=r"(r[1]) : "r"(addr));
}
__device__ __forceinline__ void ldm_x2t(uint32_t* r, uint32_t addr) {
    asm volatile("ldmatrix.sync.aligned.m8n8.x2.trans.shared.b16 {%0,%1}, [%2];"
        : "=r"(r[0]), "=r"(r[1]) : "r"(addr));
}
__device__ __forceinline__ void mma16816(float* d, const uint32_t* a, const uint32_t* b) {
    asm volatile("mma.sync.aligned.m16n8k16.row.col.f32.bf16.bf16.f32 "
        "{%0,%1,%2,%3}, {%4,%5,%6,%7}, {%8,%9}, {%0,%1,%2,%3};"
        : "+f"(d[0]), "+f"(d[1]), "+f"(d[2]), "+f"(d[3])
        : "r"(a[0]), "r"(a[1]), "r"(a[2]), "r"(a[3]), "r"(b[0]), "r"(b[1]));
}
__device__ __forceinline__ void cp_async16(uint32_t dst, const void* src) {
    asm volatile("cp.async.cg.shared.global [%0], [%1], 16;" :: "r"(dst), "l"(src));
}
__device__ __forceinline__ float ex2f(float x) {
    float r; asm("ex2.approx.ftz.f32 %0, %1;" : "=f"(r) : "f"(x)); return r;
}
__device__ __forceinline__ uint32_t packbf(float lo, float hi) {
    uint32_t r; asm("cvt.rn.bf16x2.f32 %0, %1, %2;" : "=r"(r) : "f"(hi), "f"(lo)); return r;
}
__device__ __forceinline__ float bflo(uint32_t u){ return __uint_as_float(u << 16); }
__device__ __forceinline__ float bfhi(uint32_t u){ return __uint_as_float(u & 0xffff0000u); }

// ---------------- fused prep: conv_split + prep_w + prep_past (R11-verified) -----
#define PREP_CONV_BLKS_ 4096
#define PREP_W_BLKS_    4096
#define PREP_PAST_BLKS_ 28672
#define PREP_TOTAL_BLKS_ (PREP_CONV_BLKS_ + PREP_W_BLKS_ + PREP_PAST_BLKS_)

__global__ __launch_bounds__(256) void fused_prep_kernel(
    const float* __restrict__ xsrc,
    const float* __restrict__ Wq, const float* __restrict__ Wk,
    const float* __restrict__ Wv, const float* __restrict__ Wo,
    const float* __restrict__ pk, const float* __restrict__ pv,
    const int* __restrict__ plen)
{
    __shared__ float ts[32][33];
    int bid = blockIdx.x;
    int tid = threadIdx.x;

    if (bid < PREP_CONV_BLKS_) {
        int i4 = bid * 256 + tid;
        float4 v = ((const float4*)xsrc)[i4];
        __nv_bfloat16 h0 = __float2bfloat16_rn(v.x), h1 = __float2bfloat16_rn(v.y);
        __nv_bfloat16 h2 = __float2bfloat16_rn(v.z), h3 = __float2bfloat16_rn(v.w);
        ushort4 ho, lw;
        ho.x = __bfloat16_as_ushort(h0); ho.y = __bfloat16_as_ushort(h1);
        ho.z = __bfloat16_as_ushort(h2); ho.w = __bfloat16_as_ushort(h3);
        lw.x = __bfloat16_as_ushort(__float2bfloat16_rn(v.x - __bfloat162float(h0)));
        lw.y = __bfloat16_as_ushort(__float2bfloat16_rn(v.y - __bfloat162float(h1)));
        lw.z = __bfloat16_as_ushort(__float2bfloat16_rn(v.z - __bfloat162float(h2)));
        lw.w = __bfloat16_as_ushort(__float2bfloat16_rn(v.w - __bfloat162float(h3)));
        ((ushort4*)g_x_hi)[i4] = ho;
        ((ushort4*)g_x_lo)[i4] = lw;
    } else if (bid < PREP_CONV_BLKS_ + PREP_W_BLKS_) {
        int j  = bid - PREP_CONV_BLKS_;
        int zz = j >> 10;
        int r  = j & 1023;
        int n0 = (r & 31) * 32;
        int k0 = (r >> 5) * 32;
        const float* W = (zz == 0) ? Wq : (zz == 1) ? Wk : (zz == 2) ? Wv : Wo;
        size_t base = (size_t)zz * DM_ * DM_;
        int tx = tid & 31, ty8 = tid >> 5;
        for (int i = ty8; i < 32; i += 8)
            ts[i][tx] = W[(size_t)(k0 + i) * DM_ + n0 + tx];
        __syncthreads();
        for (int i = ty8; i < 32; i += 8) {
            float v = ts[tx][i];
            __nv_bfloat16 h = __float2bfloat16_rn(v);
            __nv_bfloat16 l = __float2bfloat16_rn(v - __bfloat162float(h));
            size_t off = base + (size_t)(n0 + i) * DM_ + k0 + tx;
            g_wt_hi[off] = h;
            g_wt_lo[off] = l;
        }
    } else {
        int j  = bid - PREP_CONV_BLKS_ - PREP_W_BLKS_;
        int xb = j % 224;
        int bh = j / 224;
        int b  = bh >> 4;
        int Tp = plen[b]; Tp = Tp < 0 ? 0 : (Tp > P_ ? P_ : Tp);
        int i4 = xb * 256 + tid;
        int key = i4 >> 4;
        if (key >= Tp) return;
        size_t off = (size_t)bh * (P_*DH_) + (size_t)i4 * 4;
        float4 kv = *(const float4*)(pk + off);
        float4 vv = *(const float4*)(pv + off);
#define SPLIT4(V, HI, LO) do {                                                  \
        __nv_bfloat16 h0=__float2bfloat16_rn(V.x), h1=__float2bfloat16_rn(V.y); \
        __nv_bfloat16 h2=__float2bfloat16_rn(V.z), h3=__float2bfloat16_rn(V.w); \
        ushort4 hv, lv;                                                          \
        hv.x=__bfloat16_as_ushort(h0); hv.y=__bfloat16_as_ushort(h1);            \
        hv.z=__bfloat16_as_ushort(h2); hv.w=__bfloat16_as_ushort(h3);            \
        lv.x=__bfloat16_as_ushort(__float2bfloat16_rn(V.x-__bfloat162float(h0)));\
        lv.y=__bfloat16_as_ushort(__float2bfloat16_rn(V.y-__bfloat162float(h1)));\
        lv.z=__bfloat16_as_ushort(__float2bfloat16_rn(V.z-__bfloat162float(h2)));\
        lv.w=__bfloat16_as_ushort(__float2bfloat16_rn(V.w-__bfloat162float(h3)));\
        *(ushort4*)(HI + off) = hv; *(ushort4*)(LO + off) = lv;                  \
    } while(0)
        SPLIT4(kv, g_pkh, g_pkl);
        SPLIT4(vv, g_pvh, g_pvl);
#undef SPLIT4
    }
}

// ---------------- mma.sync QKV GEMM (128x128 tiles; R7/R11-verified) -------------
#define KT_          32
#define NCHUNK_      (DM_/KT_)
#define ROWB_        80
#define TILE_B_      (128*ROWB_)
#define STAGE_B_     (4*TILE_B_)
#define SMEM_GEMM_   (2*STAGE_B_)

__global__ void __launch_bounds__(256, 2) mma_gemm_kernel(
    const float* __restrict__ rcos, const float* __restrict__ rsin,
    const float* __restrict__ bq, const float* __restrict__ bk,
    const float* __restrict__ bv, const int* __restrict__ nc)
{
    int z    = blockIdx.z;
    int row0 = blockIdx.y * 128;
    int col0 = blockIdx.x * 128;
    int b    = row0 >> 9;
    int t0b  = row0 & 511;
    int Nn   = nc[b];
    int tid  = threadIdx.x;

    if (t0b >= Nn) return;

    const __nv_bfloat16* Ahi = g_x_hi;
    const __nv_bfloat16* Alo = g_x_lo;
    const __nv_bfloat16* Bhi = g_wt_hi + (size_t)z * DM_ * DM_;
    const __nv_bfloat16* Blo = g_wt_lo + (size_t)z * DM_ * DM_;

    extern __shared__ __align__(128) char smem[];
    uint32_t sbase = smem_u32(smem);

    int lane = tid & 31;
    int wid  = tid >> 5;
    int wm   = wid >> 2;
    int wn   = wid & 3;

    float acc[4][4][4];
#pragma unroll
    for (int i = 0; i < 4; i++)
#pragma unroll
        for (int j = 0; j < 4; j++)
#pragma unroll
            for (int q = 0; q < 4; q++) acc[i][j][q] = 0.f;

    int aRow = wm * 64 + (lane & 15);
    int aCol = (lane >> 4) << 3;
    int bRow = wn * 32 + (lane & 7);
    int bCol = ((lane >> 3) & 1) << 3;

#define LOAD_STAGE(ii) do {                                                     \
        int _i = (ii);                                                          \
        int _s = _i & 1;                                                        \
        int _k0 = _i * KT_;                                                     \
        uint32_t _sd = sbase + _s * STAGE_B_;                                   \
        _Pragma("unroll")                                                       \
        for (int _j = 0; _j < 8; _j++) {                                        \
            int _idx  = tid + _j * 256;                                         \
            int _tile = _idx >> 9;                                              \
            int _r    = (_idx >> 2) & 127;                                      \
            int _c    = _idx & 3;                                               \
            const __nv_bfloat16* _gp =                                          \
                (_tile == 0) ? Ahi : (_tile == 1) ? Alo :                       \
                (_tile == 2) ? Bhi : Blo;                                       \
            int _grow = (_tile < 2) ? (row0 + _r) : (col0 + _r);                \
            cp_async16(_sd + _tile * TILE_B_ + _r * ROWB_ + _c * 16,            \
                       _gp + (size_t)_grow * DM_ + _k0 + _c * 8);               \
        }                                                                       \
        asm volatile("cp.async.commit_group;" ::: "memory");                    \
    } while (0)

    LOAD_STAGE(0);
    for (int i = 0; i < NCHUNK_; i++) {
        if (i + 1 < NCHUNK_) {
            LOAD_STAGE(i + 1);
            asm volatile("cp.async.wait_group 1;" ::: "memory");
        } else {
            asm volatile("cp.async.wait_group 0;" ::: "memory");
        }
        __syncthreads();

        uint32_t st = sbase + (i & 1) * STAGE_B_;
#pragma unroll
        for (int kk = 0; kk < KT_; kk += 16) {
            uint32_t A[4][4], Bh[4][2], Bl[4][2];
#pragma unroll
            for (int fn = 0; fn < 4; fn++) {
                uint32_t off = (uint32_t)((bRow + fn * 8) * ROWB_ + (kk + bCol) * 2);
                ldm_x2(Bh[fn], st + 2 * TILE_B_ + off);
                ldm_x2(Bl[fn], st + 3 * TILE_B_ + off);
            }
#pragma unroll
            for (int fm = 0; fm < 4; fm++) {
                uint32_t off = (uint32_t)((aRow + fm * 16) * ROWB_ + (kk + aCol) * 2);
                ldm_x4(A[fm], st + 0 * TILE_B_ + off);
            }
#pragma unroll
            for (int fm = 0; fm < 4; fm++)
#pragma unroll
                for (int fn = 0; fn < 4; fn++) {
                    mma16816(acc[fm][fn], A[fm], Bh[fn]);
                    mma16816(acc[fm][fn], A[fm], Bl[fn]);
                }
#pragma unroll
            for (int fm = 0; fm < 4; fm++) {
                uint32_t off = (uint32_t)((aRow + fm * 16) * ROWB_ + (kk + aCol) * 2);
                ldm_x4(A[fm], st + 1 * TILE_B_ + off);
            }
#pragma unroll
            for (int fm = 0; fm < 4; fm++)
#pragma unroll
                for (int fn = 0; fn < 4; fn++)
                    mma16816(acc[fm][fn], A[fm], Bh[fn]);
        }
        __syncthreads();
    }
#undef LOAD_STAGE

    float* Cs = (float*)smem;                  // [128][132]
#pragma unroll
    for (int fm = 0; fm < 4; fm++)
#pragma unroll
        for (int fn = 0; fn < 4; fn++) {
            int m = wm * 64 + fm * 16 + (lane >> 2);
            int n = wn * 32 + fn * 8 + ((lane & 3) << 1);
            *(float2*)&Cs[m * 132 + n]       = make_float2(acc[fm][fn][0], acc[fm][fn][1]);
            *(float2*)&Cs[(m + 8) * 132 + n] = make_float2(acc[fm][fn][2], acc[fm][fn][3]);
        }
    __syncthreads();

    {
        int r    = tid >> 1;
        int hh   = tid & 1;
        int m    = row0 + r;
        int t    = m & 511;
        bool valid = (t < Nn);
        const float* Cr = Cs + r * 132 + hh * 64;
        const float* bias = ((z == 0) ? bq : (z == 1) ? bk : bv) + col0 + hh * 64;
        __nv_bfloat16 *dsth, *dstl;
        if (z == 0)      { dsth = g_qh;  dstl = g_ql;  }
        else if (z == 1) { dsth = g_knh; dstl = g_knl; }
        else             { dsth = g_vnh; dstl = g_vnl; }
        float v[64], o[64];
#pragma unroll
        for (int j = 0; j < 64; j++) v[j] = Cr[j] + bias[j];
        if (z < 2) {
#pragma unroll
            for (int d = 0; d < 32; d++) {
                float cc = rcos[(t << 6) + d];
                float ss = rsin[(t << 6) + d];
                o[d]      = v[d] * cc - v[d + 32] * ss;
                o[d + 32] = v[d + 32] * cc + v[d] * ss;
            }
            if (z == 0) {
#pragma unroll
                for (int j = 0; j < 64; j++) o[j] *= QSC_;
            }
        } else {
#pragma unroll
            for (int j = 0; j < 64; j++) o[j] = v[j];
        }
        if (!valid) {
#pragma unroll
            for (int j = 0; j < 64; j++) o[j] = 0.f;
        }
        int h = (col0 >> 6) + hh;
        size_t off = (((size_t)b * H_ + h) * T_ + t) * DH_;
#pragma unroll
        for (int j = 0; j < 64; j += 4) {
            ushort4 hv, lv;
            __nv_bfloat16 h0=__float2bfloat16_rn(o[j+0]), h1=__float2bfloat16_rn(o[j+1]);
            __nv_bfloat16 h2=__float2bfloat16_rn(o[j+2]), h3=__float2bfloat16_rn(o[j+3]);
            hv.x=__bfloat16_as_ushort(h0); hv.y=__bfloat16_as_ushort(h1);
            hv.z=__bfloat16_as_ushort(h2); hv.w=__bfloat16_as_ushort(h3);
            lv.x=__bfloat16_as_ushort(__float2bfloat16_rn(o[j+0]-__bfloat162float(h0)));
            lv.y=__bfloat16_as_ushort(__float2bfloat16_rn(o[j+1]-__bfloat162float(h1)));
            lv.z=__bfloat16_as_ushort(__float2bfloat16_rn(o[j+2]-__bfloat162float(h2)));
            lv.w=__bfloat16_as_ushort(__float2bfloat16_rn(o[j+3]-__bfloat162float(h3)));
            *(ushort4*)(dsth + off + j) = hv;
            *(ushort4*)(dstl + off + j) = lv;
        }
    }
}

// ---------------- out-proj GEMM: 128x64 tiles, grid 512 (R13-verified) -----------
#define OT_A_B_   (128*ROWB_)
#define OT_B_B_   (64*ROWB_)
#define OT_STG_   (2*OT_A_B_ + 2*OT_B_B_)
#define SMEM_OUT_ (2*OT_STG_)

__global__ void __launch_bounds__(256, 2) gemm_out64_kernel(
    const float* __restrict__ bo, float* __restrict__ Out,
    const int* __restrict__ nc)
{
    int bid  = blockIdx.x;
    int row0 = (bid >> 4) * 128;
    int col0 = (bid & 15) * 64;
    int b    = row0 >> 9;
    int t0b  = row0 & 511;
    int Nn   = nc[b];
    int tid  = threadIdx.x;

    if (t0b >= Nn) {
        float4 z4 = make_float4(0.f, 0.f, 0.f, 0.f);
        for (int i = tid; i < 128 * 16; i += 256) {
            int r = i >> 4, c4 = (i & 15) << 2;
            *(float4*)(Out + (size_t)(row0 + r) * DM_ + col0 + c4) = z4;
        }
        return;
    }

    extern __shared__ __align__(128) char smem[];
    uint32_t sbase = smem_u32(smem);

    int lane = tid & 31;
    int wid  = tid >> 5;
    int wm   = wid >> 2;
    int wn   = wid & 3;

    float acc[4][2][4];
#pragma unroll
    for (int i = 0; i < 4; i++)
#pragma unroll
        for (int j = 0; j < 2; j++)
#pragma unroll
            for (int q = 0; q < 4; q++) acc[i][j][q] = 0.f;

    int aRow = wm * 64 + (lane & 15);
    int aCol = (lane >> 4) << 3;
    int bRow = wn * 16 + (lane & 7);
    int bCol = ((lane >> 3) & 1) << 3;

#define OLOAD_STAGE(ii) do {                                                    \
        int _i = (ii);                                                          \
        int _s = _i & 1;                                                        \
        int _k0 = _i * KT_;                                                     \
        uint32_t _sd = sbase + _s * OT_STG_;                                    \
        _Pragma("unroll")                                                       \
        for (int _j = 0; _j < 6; _j++) {                                        \
            int _idx = tid + _j * 256;                                          \
            if (_idx < 1024) {                                                  \
                int _tile = _idx >> 9;                                          \
                int _r    = (_idx >> 2) & 127;                                  \
                int _c    = _idx & 3;                                           \
                const __nv_bfloat16* _gp = _tile ? g_at_lo : g_at_hi;           \
                cp_async16(_sd + _tile * OT_A_B_ + _r * ROWB_ + _c * 16,        \
                           _gp + (size_t)(row0 + _r) * DM_ + _k0 + _c * 8);     \
            } else {                                                            \
                int _q    = _idx - 1024;                                        \
                int _tile = _q >> 8;                                            \
                int _r    = (_q >> 2) & 63;                                     \
                int _c    = _q & 3;                                             \
                const __nv_bfloat16* _gp = (_tile ? g_wt_lo : g_wt_hi)          \
                                           + (size_t)3 * DM_ * DM_;             \
                cp_async16(_sd + 2 * OT_A_B_ + _tile * OT_B_B_                  \
                               + _r * ROWB_ + _c * 16,                          \
                           _gp + (size_t)(col0 + _r) * DM_ + _k0 + _c * 8);     \
            }                                                                   \
        }                                                                       \
        asm volatile("cp.async.commit_group;" ::: "memory");                    \
    } while (0)

    OLOAD_STAGE(0);
    for (int i = 0; i < NCHUNK_; i++) {
        if (i + 1 < NCHUNK_) {
            OLOAD_STAGE(i + 1);
            asm volatile("cp.async.wait_group 1;" ::: "memory");
        } else {
            asm volatile("cp.async.wait_group 0;" ::: "memory");
        }
        __syncthreads();

        uint32_t st = sbase + (i & 1) * OT_STG_;
        uint32_t stB = st + 2 * OT_A_B_;
#pragma unroll
        for (int kk = 0; kk < KT_; kk += 16) {
            uint32_t A[4][4], Bh[2][2], Bl[2][2];
#pragma unroll
            for (int fn = 0; fn < 2; fn++) {
                uint32_t off = (uint32_t)((bRow + fn * 8) * ROWB_ + (kk + bCol) * 2);
                ldm_x2(Bh[fn], stB + off);
                ldm_x2(Bl[fn], stB + OT_B_B_ + off);
            }
#pragma unroll
            for (int fm = 0; fm < 4; fm++) {
                uint32_t off = (uint32_t)((aRow + fm * 16) * ROWB_ + (kk + aCol) * 2);
                ldm_x4(A[fm], st + off);
            }
#pragma unroll
            for (int fm = 0; fm < 4; fm++)
#pragma unroll
                for (int fn = 0; fn < 2; fn++) {
                    mma16816(acc[fm][fn], A[fm], Bh[fn]);
                    mma16816(acc[fm][fn], A[fm], Bl[fn]);
                }
#pragma unroll
            for (int fm = 0; fm < 4; fm++) {
                uint32_t off = (uint32_t)((aRow + fm * 16) * ROWB_ + (kk + aCol) * 2);
                ldm_x4(A[fm], st + OT_A_B_ + off);
            }
#pragma unroll
            for (int fm = 0; fm < 4; fm++)
#pragma unroll
                for (int fn = 0; fn < 2; fn++)
                    mma16816(acc[fm][fn], A[fm], Bh[fn]);
        }
        __syncthreads();
    }
#undef OLOAD_STAGE

    float* Cs = (float*)smem;                  // [128][68]
#pragma unroll
    for (int fm = 0; fm < 4; fm++)
#pragma unroll
        for (int fn = 0; fn < 2; fn++) {
            int m = wm * 64 + fm * 16 + (lane >> 2);
            int n = wn * 16 + fn * 8 + ((lane & 3) << 1);
            *(float2*)&Cs[m * 68 + n]       = make_float2(acc[fm][fn][0], acc[fm][fn][1]);
            *(float2*)&Cs[(m + 8) * 68 + n] = make_float2(acc[fm][fn][2], acc[fm][fn][3]);
        }
    __syncthreads();

    {
        int r    = tid >> 1;
        int hh   = tid & 1;
        int m    = row0 + r;
        int t    = m & 511;
        bool valid = (t < Nn);
        const float* Cr = Cs + r * 68 + hh * 32;
        float* dst = Out + (size_t)m * DM_ + col0 + hh * 32;
        const float* bb = bo + col0 + hh * 32;
#pragma unroll
        for (int c = 0; c < 32; c += 4) {
            float4 o;
            o.x = valid ? Cr[c+0] + bb[c+0] : 0.f;
            o.y = valid ? Cr[c+1] + bb[c+1] : 0.f;
            o.z = valid ? Cr[c+2] + bb[c+2] : 0.f;
            o.w = valid ? Cr[c+3] + bb[c+3] : 0.f;
            *(float4*)(dst + c) = o;
        }
    }
}

// ---------------- Flash attention: reg-lean (Q reloaded per iter), 2 CTAs/SM -----
#define SMEM_ATTN_ 110592

__global__ void __launch_bounds__(256, 2) attn_mma_kernel(
    const int* __restrict__ plen, const int* __restrict__ nc)
{
    extern __shared__ __align__(128) char smem[];
    const uint32_t sbase = smem_u32(smem);

    int b = blockIdx.z, h = blockIdx.y, t0 = blockIdx.x * 128;
    int Nn = nc[b];
    if (t0 >= Nn) return;
    int Tp = plen[b]; Tp = Tp < 0 ? 0 : (Tp > P_ ? P_ : Tp);
    int Ltot   = Tp + Nn;
    int nPast  = (Tp + 63) >> 6;
    int newLen = Ltot - P_;
    int nNew   = newLen > 0 ? (newLen + 63) >> 6 : 0;
    int nblk   = nPast + nNew;
    int Tpad   = nPast << 6;
    int Z      = (P_ < Ltot ? P_ : Ltot) - Tpad; if (Z < 0) Z = 0;

    int tid = threadIdx.x, lane = tid & 31, wid = tid >> 5;
    size_t bh = (size_t)b * H_ + h;

    {
        const __nv_bfloat16* qh = g_qh + (bh * T_ + t0) * DH_;
        const __nv_bfloat16* ql = g_ql + (bh * T_ + t0) * DH_;
#pragma unroll
        for (int u = 0; u < 8; u++) {
            int idx = tid + u * 256;
            int arr = idx >> 10;
            int rem = idx & 1023;
            int row = rem >> 3, c = rem & 7;
            const __nv_bfloat16* src = (arr ? ql : qh) + (size_t)row * DH_ + c * 8;
            cp_async16(sbase + arr * 18432 + row * 144 + c * 16, src);
        }
        asm volatile("cp.async.commit_group;" ::: "memory");
    }

    auto load_stage = [&](int i) {
        uint32_t SB = sbase + 36864 + (i & 1) * 36864;
        bool past = i < nPast;
        int j0 = past ? (i << 6) : (P_ + ((i - nPast) << 6));
        const __nv_bfloat16 *kh, *kl, *vh, *vl; size_t rb;
        if (past) { kh=g_pkh; kl=g_pkl; vh=g_pvh; vl=g_pvl; rb = bh * P_ + j0; }
        else      { kh=g_knh; kl=g_knl; vh=g_vnh; vl=g_vnl; rb = bh * T_ + (j0 - P_); }
#pragma unroll
        for (int u = 0; u < 8; u++) {
            int idx = tid + u * 256;
            int arr = idx >> 9;
            int rem = idx & 511;
            int row = rem >> 3, c = rem & 7;
            uint32_t dst = SB + arr * 9216 + row * 144 + c * 16;
            if (past && (j0 + row) >= Tp) {
                asm volatile("st.shared.v4.b32 [%0], {%1,%1,%1,%1};"
                             :: "r"(dst), "r"(0) : "memory");
            } else {
                const __nv_bfloat16* srcb = arr==0?kh:arr==1?kl:arr==2?vh:vl;
                cp_async16(dst, srcb + (rb + row) * DH_ + c * 8);
            }
        }
        asm volatile("cp.async.commit_group;" ::: "memory");
    };

    float m0 = -1e30f, m1 = -1e30f, l0 = 0.f, l1 = 0.f;
    float O[8][4];
#pragma unroll
    for (int nf = 0; nf < 8; nf++)
#pragma unroll
        for (int q = 0; q < 4; q++) O[nf][q] = 0.f;

    // per-thread Q fragment smem offsets (reloaded every iteration)
    uint32_t qfo[4];
#pragma unroll
    for (int kk = 0; kk < 4; kk++)
        qfo[kk] = (uint32_t)((wid * 16 + (lane & 15)) * 144
                             + (kk * 16 + ((lane >> 4) << 3)) * 2);

    if (nblk > 0) {
        load_stage(0);
        asm volatile("cp.async.wait_group 1;" ::: "memory");
        __syncthreads();
    } else {
        asm volatile("cp.async.wait_group 0;" ::: "memory");
    }

    for (int i = 0; i < nblk; i++) {
        __syncthreads();
        if (i + 1 < nblk) {
            load_stage(i + 1);
            asm volatile("cp.async.wait_group 1;" ::: "memory");
        } else {
            asm volatile("cp.async.wait_group 0;" ::: "memory");
        }
        __syncthreads();

        int j0 = (i < nPast) ? (i << 6) : (P_ + ((i - nPast) << 6));
        uint32_t SB = sbase + 36864 + (i & 1) * 36864;

        float S[8][4];
#pragma unroll
        for (int nf = 0; nf < 8; nf++)
#pragma unroll
            for (int q = 0; q < 4; q++) S[nf][q] = 0.f;

        // ---- pass A: Qh·(Kh + Kl) ----
        {
            uint32_t Qf[4][4];
#pragma unroll
            for (int kk = 0; kk < 4; kk++) ldm_x4(Qf[kk], sbase + qfo[kk]);
#pragma unroll
            for (int nf = 0; nf < 8; nf++) {
                uint32_t kfh[4][2], kfl[4][2];
#pragma unroll
                for (int kk = 0; kk < 4; kk++) {
                    uint32_t off = (uint32_t)((nf * 8 + (lane & 7)) * 144
                                              + (kk * 16 + (((lane >> 3) & 1) << 3)) * 2);
                    ldm_x2(kfh[kk], SB + off);
                    ldm_x2(kfl[kk], SB + 9216 + off);
                }
#pragma unroll
                for (int kk = 0; kk < 4; kk++) {
                    mma16816(S[nf], Qf[kk], kfh[kk]);
                    mma16816(S[nf], Qf[kk], kfl[kk]);
                }
            }
        }
        // ---- pass B: Ql·Kh ----
        {
            uint32_t Qf[4][4];
#pragma unroll
            for (int kk = 0; kk < 4; kk++) ldm_x4(Qf[kk], sbase + 18432 + qfo[kk]);
#pragma unroll
            for (int nf = 0; nf < 8; nf++) {
                uint32_t kfh[4][2];
#pragma unroll
                for (int kk = 0; kk < 4; kk++) {
                    uint32_t off = (uint32_t)((nf * 8 + (lane & 7)) * 144
                                              + (kk * 16 + (((lane >> 3) & 1) << 3)) * 2);
                    ldm_x2(kfh[kk], SB + off);
                }
#pragma unroll
                for (int kk = 0; kk < 4; kk++)
                    mma16816(S[nf], Qf[kk], kfh[kk]);
            }
        }

#pragma unroll
        for (int nf = 0; nf < 8; nf++) {
            int keyc = j0 + nf * 8 + ((lane & 3) << 1);
            if (keyc     >= Ltot) { S[nf][0] = -1e9f; S[nf][2] = -1e9f; }
            if (keyc + 1 >= Ltot) { S[nf][1] = -1e9f; S[nf][3] = -1e9f; }
        }

        float mx0 = -1e30f, mx1 = -1e30f;
#pragma unroll
        for (int nf = 0; nf < 8; nf++) {
            mx0 = fmaxf(mx0, fmaxf(S[nf][0], S[nf][1]));
            mx1 = fmaxf(mx1, fmaxf(S[nf][2], S[nf][3]));
        }
        mx0 = fmaxf(mx0, __shfl_xor_sync(0xffffffffu, mx0, 1));
        mx0 = fmaxf(mx0, __shfl_xor_sync(0xffffffffu, mx0, 2));
        mx1 = fmaxf(mx1, __shfl_xor_sync(0xffffffffu, mx1, 1));
        mx1 = fmaxf(mx1, __shfl_xor_sync(0xffffffffu, mx1, 2));
        float nm0 = fmaxf(m0, mx0), nm1 = fmaxf(m1, mx1);
        float a0 = ex2f(m0 - nm0), a1 = ex2f(m1 - nm1);
        m0 = nm0; m1 = nm1;
        float rs0 = 0.f, rs1 = 0.f;
#pragma unroll
        for (int nf = 0; nf < 8; nf++) {
            S[nf][0] = ex2f(S[nf][0] - nm0);
            S[nf][1] = ex2f(S[nf][1] - nm0);
            S[nf][2] = ex2f(S[nf][2] - nm1);
            S[nf][3] = ex2f(S[nf][3] - nm1);
            rs0 += S[nf][0] + S[nf][1];
            rs1 += S[nf][2] + S[nf][3];
        }
        rs0 += __shfl_xor_sync(0xffffffffu, rs0, 1);
        rs0 += __shfl_xor_sync(0xffffffffu, rs0, 2);
        rs1 += __shfl_xor_sync(0xffffffffu, rs1, 1);
        rs1 += __shfl_xor_sync(0xffffffffu, rs1, 2);
        l0 = l0 * a0 + rs0;
        l1 = l1 * a1 + rs1;
#pragma unroll
        for (int nf = 0; nf < 8; nf++) {
            O[nf][0] *= a0; O[nf][1] *= a0;
            O[nf][2] *= a1; O[nf][3] *= a1;
        }

        uint32_t Ph[4][4], Pl[4][4];
#pragma unroll
        for (int kk = 0; kk < 4; kk++) {
            float p0 = S[2*kk][0],   p1 = S[2*kk][1],   p2 = S[2*kk][2],   p3 = S[2*kk][3];
            float q0 = S[2*kk+1][0], q1 = S[2*kk+1][1], q2 = S[2*kk+1][2], q3 = S[2*kk+1][3];
            uint32_t u;
            u = packbf(p0, p1); Ph[kk][0] = u; Pl[kk][0] = packbf(p0 - bflo(u), p1 - bfhi(u));
            u = packbf(p2, p3); Ph[kk][1] = u; Pl[kk][1] = packbf(p2 - bflo(u), p3 - bfhi(u));
            u = packbf(q0, q1); Ph[kk][2] = u; Pl[kk][2] = packbf(q0 - bflo(u), q1 - bfhi(u));
            u = packbf(q2, q3); Ph[kk][3] = u; Pl[kk][3] = packbf(q2 - bflo(u), q3 - bfhi(u));
        }

#pragma unroll
        for (int nf = 0; nf < 8; nf++) {
            uint32_t vfh[4][2], vfl[4][2];
#pragma unroll
            for (int kk = 0; kk < 4; kk++) {
                uint32_t off = (uint32_t)((kk * 16 + (lane & 15)) * 144 + nf * 16);
                ldm_x2t(vfh[kk], SB + 18432 + off);
                ldm_x2t(vfl[kk], SB + 27648 + off);
            }
#pragma unroll
            for (int kk = 0; kk < 4; kk++) {
                mma16816(O[nf], Ph[kk], vfh[kk]);
                mma16816(O[nf], Ph[kk], vfl[kk]);
                mma16816(O[nf], Pl[kk], vfh[kk]);
            }
        }
    }

    if (Z > 0) {
        float nm0 = fmaxf(m0, 0.f), nm1 = fmaxf(m1, 0.f);
        float a0 = ex2f(m0 - nm0), a1 = ex2f(m1 - nm1);
        l0 = l0 * a0 + (float)Z * ex2f(-nm0);
        l1 = l1 * a1 + (float)Z * ex2f(-nm1);
#pragma unroll
        for (int nf = 0; nf < 8; nf++) {
            O[nf][0] *= a0; O[nf][1] *= a0;
            O[nf][2] *= a1; O[nf][3] *= a1;
        }
    }

    float inv0 = 1.f / l0, inv1 = 1.f / l1;
    float* Os = (float*)smem;
    __syncthreads();
    {
        int r0 = wid * 16 + (lane >> 2);
        int cb = (lane & 3) << 1;
#pragma unroll
        for (int nf = 0; nf < 8; nf++) {
            *(float2*)&Os[r0 * 68 + nf * 8 + cb] =
                make_float2(O[nf][0] * inv0, O[nf][1] * inv0);
            *(float2*)&Os[(r0 + 8) * 68 + nf * 8 + cb] =
                make_float2(O[nf][2] * inv1, O[nf][3] * inv1);
        }
    }
    __syncthreads();
    {
        int r = tid >> 1;
        int half = (tid & 1) * 32;
        int t = t0 + r;
        size_t orow = ((size_t)b * T_ + t) * DM_ + h * DH_ + half;
        const float* Or = Os + r * 68 + half;
#pragma unroll
        for (int j = 0; j < 32; j += 4) {
            float v0 = Or[j], v1 = Or[j+1], v2 = Or[j+2], v3 = Or[j+3];
            __nv_bfloat16 h0=__float2bfloat16_rn(v0), h1=__float2bfloat16_rn(v1);
            __nv_bfloat16 h2=__float2bfloat16_rn(v2), h3=__float2bfloat16_rn(v3);
            ushort4 hv, lv;
            hv.x=__bfloat16_as_ushort(h0); hv.y=__bfloat16_as_ushort(h1);
            hv.z=__bfloat16_as_ushort(h2); hv.w=__bfloat16_as_ushort(h3);
            lv.x=__bfloat16_as_ushort(__float2bfloat16_rn(v0-__bfloat162float(h0)));
            lv.y=__bfloat16_as_ushort(__float2bfloat16_rn(v1-__bfloat162float(h1)));
            lv.z=__bfloat16_as_ushort(__float2bfloat16_rn(v2-__bfloat162float(h2)));
            lv.w=__bfloat16_as_ushort(__float2bfloat16_rn(v3-__bfloat162float(h3)));
            *(ushort4*)(g_at_hi + orow + j) = hv;
            *(ushort4*)(g_at_lo + orow + j) = lv;
        }
    }
}

// ---------------- launch ----------------
extern "C" void kernel_launch(void* const* d_in, const int* in_sizes, int n_in,
                              void* d_out, int out_size)
{
    const float* x   = (const float*)d_in[0];
    const float* rc  = (const float*)d_in[1];
    const float* rs  = (const float*)d_in[2];
    const float* pk  = (const float*)d_in[3];
    const float* pv  = (const float*)d_in[4];
    const int*   pl  = (const int*)  d_in[5];
    const int*   nc  = (const int*)  d_in[7];
    const float* Wq  = (const float*)d_in[8];
    const float* bq  = (const float*)d_in[9];
    const float* Wk  = (const float*)d_in[10];
    const float* bk  = (const float*)d_in[11];
    const float* Wv  = (const float*)d_in[12];
    const float* bv  = (const float*)d_in[13];
    const float* Wo  = (const float*)d_in[14];
    const float* bo  = (const float*)d_in[15];
    float* out = (float*)d_out;

    cudaFuncSetAttribute(mma_gemm_kernel,
                         cudaFuncAttributeMaxDynamicSharedMemorySize, SMEM_GEMM_);
    cudaFuncSetAttribute(gemm_out64_kernel,
                         cudaFuncAttributeMaxDynamicSharedMemorySize, SMEM_OUT_);
    cudaFuncSetAttribute(attn_mma_kernel,
                         cudaFuncAttributeMaxDynamicSharedMemorySize, SMEM_ATTN_);

    fused_prep_kernel<<<PREP_TOTAL_BLKS_, 256>>>(x, Wq, Wk, Wv, Wo, pk, pv, pl);
    mma_gemm_kernel<<<dim3(8, 32, 3), 256, SMEM_GEMM_>>>(rc, rs, bq, bk, bv, nc);
    attn_mma_kernel<<<dim3(T_/128, H_, B_), 256, SMEM_ATTN_>>>(pl, nc);
    gemm_out64_kernel<<<512, 256, SMEM_OUT_>>>(bo, out, nc);
}

// round 16
// speedup vs baseline: 1.0288x; 1.0288x over previous
#include <cuda_runtime.h>
#include <cuda_bf16.h>
#include <math.h>
#include <stdint.h>

#define B_   8
#define T_   512
#define DM_  1024
#define H_   16
#define DH_  64
#define P_   3584
#define BT_  (B_*T_)       // 4096
#define BHTD_ (B_*H_*T_*DH_)   // 4194304
#define BHPD_ (B_*H_*P_*DH_)   // 29360128
#define QSC_ 0.18033688011112042f   // 0.125 * log2(e): scores in log2 units

// ---------------- scratch (device globals; zero-initialized at load) ----------------
__device__ __nv_bfloat16 g_x_hi[BT_*DM_];
__device__ __nv_bfloat16 g_x_lo[BT_*DM_];
__device__ __nv_bfloat16 g_at_hi[BT_*DM_];
__device__ __nv_bfloat16 g_at_lo[BT_*DM_];
__device__ __nv_bfloat16 g_wt_hi[4*DM_*DM_];
__device__ __nv_bfloat16 g_wt_lo[4*DM_*DM_];
__device__ __nv_bfloat16 g_qh [BHTD_+64*DH_];
__device__ __nv_bfloat16 g_ql [BHTD_+64*DH_];
__device__ __nv_bfloat16 g_knh[BHTD_+64*DH_];
__device__ __nv_bfloat16 g_knl[BHTD_+64*DH_];
__device__ __nv_bfloat16 g_vnh[BHTD_+64*DH_];
__device__ __nv_bfloat16 g_vnl[BHTD_+64*DH_];
__device__ __nv_bfloat16 g_pkh[BHPD_];
__device__ __nv_bfloat16 g_pkl[BHPD_];
__device__ __nv_bfloat16 g_pvh[BHPD_];
__device__ __nv_bfloat16 g_pvl[BHPD_];

// ---------------- helpers ----------------
__device__ __forceinline__ uint32_t smem_u32(const void* p) {
    uint32_t a;
    asm("{ .reg .u64 t; cvta.to.shared.u64 t, %1; cvt.u32.u64 %0, t; }" : "=r"(a) : "l"(p));
    return a;
}
__device__ __forceinline__ void ldm_x4(uint32_t* r, uint32_t addr) {
    asm volatile("ldmatrix.sync.aligned.m8n8.x4.shared.b16 {%0,%1,%2,%3}, [%4];"
        : "=r"(r[0]), "=r"(r[1]), "=r"(r[2]), "=r"(r[3]) : "r"(addr));
}
__device__ __forceinline__ void ldm_x2(uint32_t* r, uint32_t addr) {
    asm volatile("ldmatrix.sync.aligned.m8n8.x2.shared.b16 {%0,%1}, [%2];"
        : "=r"(r[0]), "=r"(r[1]) : "r"(addr));
}
__device__ __forceinline__ void ldm_x2t(uint32_t* r, uint32_t addr) {
    asm volatile("ldmatrix.sync.aligned.m8n8.x2.trans.shared.b16 {%0,%1}, [%2];"
        : "=r"(r[0]), "=r"(r[1]) : "r"(addr));
}
__device__ __forceinline__ void mma16816(float* d, const uint32_t* a, const uint32_t* b) {
    asm volatile("mma.sync.aligned.m16n8k16.row.col.f32.bf16.bf16.f32 "
        "{%0,%1,%2,%3}, {%4,%5,%6,%7}, {%8,%9}, {%0,%1,%2,%3};"
        : "+f"(d[0]), "+f"(d[1]), "+f"(d[2]), "+f"(d[3])
        : "r"(a[0]), "r"(a[1]), "r"(a[2]), "r"(a[3]), "r"(b[0]), "r"(b[1]));
}
__device__ __forceinline__ void cp_async16(uint32_t dst, const void* src) {
    asm volatile("cp.async.cg.shared.global [%0], [%1], 16;" :: "r"(dst), "l"(src));
}
__device__ __forceinline__ float ex2f(float x) {
    float r; asm("ex2.approx.ftz.f32 %0, %1;" : "=f"(r) : "f"(x)); return r;
}
__device__ __forceinline__ uint32_t packbf(float lo, float hi) {
    uint32_t r; asm("cvt.rn.bf16x2.f32 %0, %1, %2;" : "=r"(r) : "f"(hi), "f"(lo)); return r;
}
__device__ __forceinline__ float bflo(uint32_t u){ return __uint_as_float(u << 16); }
__device__ __forceinline__ float bfhi(uint32_t u){ return __uint_as_float(u & 0xffff0000u); }

// ---------------- fused prep: conv_split + prep_w + prep_past (R11-verified) -----
#define PREP_CONV_BLKS_ 4096
#define PREP_W_BLKS_    4096
#define PREP_PAST_BLKS_ 28672
#define PREP_TOTAL_BLKS_ (PREP_CONV_BLKS_ + PREP_W_BLKS_ + PREP_PAST_BLKS_)

__global__ __launch_bounds__(256) void fused_prep_kernel(
    const float* __restrict__ xsrc,
    const float* __restrict__ Wq, const float* __restrict__ Wk,
    const float* __restrict__ Wv, const float* __restrict__ Wo,
    const float* __restrict__ pk, const float* __restrict__ pv,
    const int* __restrict__ plen)
{
    __shared__ float ts[32][33];
    int bid = blockIdx.x;
    int tid = threadIdx.x;

    if (bid < PREP_CONV_BLKS_) {
        int i4 = bid * 256 + tid;
        float4 v = ((const float4*)xsrc)[i4];
        __nv_bfloat16 h0 = __float2bfloat16_rn(v.x), h1 = __float2bfloat16_rn(v.y);
        __nv_bfloat16 h2 = __float2bfloat16_rn(v.z), h3 = __float2bfloat16_rn(v.w);
        ushort4 ho, lw;
        ho.x = __bfloat16_as_ushort(h0); ho.y = __bfloat16_as_ushort(h1);
        ho.z = __bfloat16_as_ushort(h2); ho.w = __bfloat16_as_ushort(h3);
        lw.x = __bfloat16_as_ushort(__float2bfloat16_rn(v.x - __bfloat162float(h0)));
        lw.y = __bfloat16_as_ushort(__float2bfloat16_rn(v.y - __bfloat162float(h1)));
        lw.z = __bfloat16_as_ushort(__float2bfloat16_rn(v.z - __bfloat162float(h2)));
        lw.w = __bfloat16_as_ushort(__float2bfloat16_rn(v.w - __bfloat162float(h3)));
        ((ushort4*)g_x_hi)[i4] = ho;
        ((ushort4*)g_x_lo)[i4] = lw;
    } else if (bid < PREP_CONV_BLKS_ + PREP_W_BLKS_) {
        int j  = bid - PREP_CONV_BLKS_;
        int zz = j >> 10;
        int r  = j & 1023;
        int n0 = (r & 31) * 32;
        int k0 = (r >> 5) * 32;
        const float* W = (zz == 0) ? Wq : (zz == 1) ? Wk : (zz == 2) ? Wv : Wo;
        size_t base = (size_t)zz * DM_ * DM_;
        int tx = tid & 31, ty8 = tid >> 5;
        for (int i = ty8; i < 32; i += 8)
            ts[i][tx] = W[(size_t)(k0 + i) * DM_ + n0 + tx];
        __syncthreads();
        for (int i = ty8; i < 32; i += 8) {
            float v = ts[tx][i];
            __nv_bfloat16 h = __float2bfloat16_rn(v);
            __nv_bfloat16 l = __float2bfloat16_rn(v - __bfloat162float(h));
            size_t off = base + (size_t)(n0 + i) * DM_ + k0 + tx;
            g_wt_hi[off] = h;
            g_wt_lo[off] = l;
        }
    } else {
        int j  = bid - PREP_CONV_BLKS_ - PREP_W_BLKS_;
        int xb = j % 224;
        int bh = j / 224;
        int b  = bh >> 4;
        int Tp = plen[b]; Tp = Tp < 0 ? 0 : (Tp > P_ ? P_ : Tp);
        int i4 = xb * 256 + tid;
        int key = i4 >> 4;
        if (key >= Tp) return;
        size_t off = (size_t)bh * (P_*DH_) + (size_t)i4 * 4;
        float4 kv = *(const float4*)(pk + off);
        float4 vv = *(const float4*)(pv + off);
#define SPLIT4(V, HI, LO) do {                                                  \
        __nv_bfloat16 h0=__float2bfloat16_rn(V.x), h1=__float2bfloat16_rn(V.y); \
        __nv_bfloat16 h2=__float2bfloat16_rn(V.z), h3=__float2bfloat16_rn(V.w); \
        ushort4 hv, lv;                                                          \
        hv.x=__bfloat16_as_ushort(h0); hv.y=__bfloat16_as_ushort(h1);            \
        hv.z=__bfloat16_as_ushort(h2); hv.w=__bfloat16_as_ushort(h3);            \
        lv.x=__bfloat16_as_ushort(__float2bfloat16_rn(V.x-__bfloat162float(h0)));\
        lv.y=__bfloat16_as_ushort(__float2bfloat16_rn(V.y-__bfloat162float(h1)));\
        lv.z=__bfloat16_as_ushort(__float2bfloat16_rn(V.z-__bfloat162float(h2)));\
        lv.w=__bfloat16_as_ushort(__float2bfloat16_rn(V.w-__bfloat162float(h3)));\
        *(ushort4*)(HI + off) = hv; *(ushort4*)(LO + off) = lv;                  \
    } while(0)
        SPLIT4(kv, g_pkh, g_pkl);
        SPLIT4(vv, g_pvh, g_pvl);
#undef SPLIT4
    }
}

// ---------------- mma.sync QKV GEMM (128x128 tiles; R7/R13-verified) -------------
#define KT_          32
#define NCHUNK_      (DM_/KT_)
#define ROWB_        80
#define TILE_B_      (128*ROWB_)
#define STAGE_B_     (4*TILE_B_)
#define SMEM_GEMM_   (2*STAGE_B_)

__global__ void __launch_bounds__(256, 2) mma_gemm_kernel(
    const float* __restrict__ rcos, const float* __restrict__ rsin,
    const float* __restrict__ bq, const float* __restrict__ bk,
    const float* __restrict__ bv, const int* __restrict__ nc)
{
    int z    = blockIdx.z;
    int row0 = blockIdx.y * 128;
    int col0 = blockIdx.x * 128;
    int b    = row0 >> 9;
    int t0b  = row0 & 511;
    int Nn   = nc[b];
    int tid  = threadIdx.x;

    if (t0b >= Nn) return;

    const __nv_bfloat16* Ahi = g_x_hi;
    const __nv_bfloat16* Alo = g_x_lo;
    const __nv_bfloat16* Bhi = g_wt_hi + (size_t)z * DM_ * DM_;
    const __nv_bfloat16* Blo = g_wt_lo + (size_t)z * DM_ * DM_;

    extern __shared__ __align__(128) char smem[];
    uint32_t sbase = smem_u32(smem);

    int lane = tid & 31;
    int wid  = tid >> 5;
    int wm   = wid >> 2;
    int wn   = wid & 3;

    float acc[4][4][4];
#pragma unroll
    for (int i = 0; i < 4; i++)
#pragma unroll
        for (int j = 0; j < 4; j++)
#pragma unroll
            for (int q = 0; q < 4; q++) acc[i][j][q] = 0.f;

    int aRow = wm * 64 + (lane & 15);
    int aCol = (lane >> 4) << 3;
    int bRow = wn * 32 + (lane & 7);
    int bCol = ((lane >> 3) & 1) << 3;

#define LOAD_STAGE(ii) do {                                                     \
        int _i = (ii);                                                          \
        int _s = _i & 1;                                                        \
        int _k0 = _i * KT_;                                                     \
        uint32_t _sd = sbase + _s * STAGE_B_;                                   \
        _Pragma("unroll")                                                       \
        for (int _j = 0; _j < 8; _j++) {                                        \
            int _idx  = tid + _j * 256;                                         \
            int _tile = _idx >> 9;                                              \
            int _r    = (_idx >> 2) & 127;                                      \
            int _c    = _idx & 3;                                               \
            const __nv_bfloat16* _gp =                                          \
                (_tile == 0) ? Ahi : (_tile == 1) ? Alo :                       \
                (_tile == 2) ? Bhi : Blo;                                       \
            int _grow = (_tile < 2) ? (row0 + _r) : (col0 + _r);                \
            cp_async16(_sd + _tile * TILE_B_ + _r * ROWB_ + _c * 16,            \
                       _gp + (size_t)_grow * DM_ + _k0 + _c * 8);               \
        }                                                                       \
        asm volatile("cp.async.commit_group;" ::: "memory");                    \
    } while (0)

    LOAD_STAGE(0);
    for (int i = 0; i < NCHUNK_; i++) {
        if (i + 1 < NCHUNK_) {
            LOAD_STAGE(i + 1);
            asm volatile("cp.async.wait_group 1;" ::: "memory");
        } else {
            asm volatile("cp.async.wait_group 0;" ::: "memory");
        }
        __syncthreads();

        uint32_t st = sbase + (i & 1) * STAGE_B_;
#pragma unroll
        for (int kk = 0; kk < KT_; kk += 16) {
            uint32_t A[4][4], Bh[4][2], Bl[4][2];
#pragma unroll
            for (int fn = 0; fn < 4; fn++) {
                uint32_t off = (uint32_t)((bRow + fn * 8) * ROWB_ + (kk + bCol) * 2);
                ldm_x2(Bh[fn], st + 2 * TILE_B_ + off);
                ldm_x2(Bl[fn], st + 3 * TILE_B_ + off);
            }
#pragma unroll
            for (int fm = 0; fm < 4; fm++) {
                uint32_t off = (uint32_t)((aRow + fm * 16) * ROWB_ + (kk + aCol) * 2);
                ldm_x4(A[fm], st + 0 * TILE_B_ + off);
            }
#pragma unroll
            for (int fm = 0; fm < 4; fm++)
#pragma unroll
                for (int fn = 0; fn < 4; fn++) {
                    mma16816(acc[fm][fn], A[fm], Bh[fn]);
                    mma16816(acc[fm][fn], A[fm], Bl[fn]);
                }
#pragma unroll
            for (int fm = 0; fm < 4; fm++) {
                uint32_t off = (uint32_t)((aRow + fm * 16) * ROWB_ + (kk + aCol) * 2);
                ldm_x4(A[fm], st + 1 * TILE_B_ + off);
            }
#pragma unroll
            for (int fm = 0; fm < 4; fm++)
#pragma unroll
                for (int fn = 0; fn < 4; fn++)
                    mma16816(acc[fm][fn], A[fm], Bh[fn]);
        }
        __syncthreads();
    }
#undef LOAD_STAGE

    float* Cs = (float*)smem;                  // [128][132]
#pragma unroll
    for (int fm = 0; fm < 4; fm++)
#pragma unroll
        for (int fn = 0; fn < 4; fn++) {
            int m = wm * 64 + fm * 16 + (lane >> 2);
            int n = wn * 32 + fn * 8 + ((lane & 3) << 1);
            *(float2*)&Cs[m * 132 + n]       = make_float2(acc[fm][fn][0], acc[fm][fn][1]);
            *(float2*)&Cs[(m + 8) * 132 + n] = make_float2(acc[fm][fn][2], acc[fm][fn][3]);
        }
    __syncthreads();

    {
        int r    = tid >> 1;
        int hh   = tid & 1;
        int m    = row0 + r;
        int t    = m & 511;
        bool valid = (t < Nn);
        const float* Cr = Cs + r * 132 + hh * 64;
        const float* bias = ((z == 0) ? bq : (z == 1) ? bk : bv) + col0 + hh * 64;
        __nv_bfloat16 *dsth, *dstl;
        if (z == 0)      { dsth = g_qh;  dstl = g_ql;  }
        else if (z == 1) { dsth = g_knh; dstl = g_knl; }
        else             { dsth = g_vnh; dstl = g_vnl; }
        float v[64], o[64];
#pragma unroll
        for (int j = 0; j < 64; j++) v[j] = Cr[j] + bias[j];
        if (z < 2) {
#pragma unroll
            for (int d = 0; d < 32; d++) {
                float cc = rcos[(t << 6) + d];
                float ss = rsin[(t << 6) + d];
                o[d]      = v[d] * cc - v[d + 32] * ss;
                o[d + 32] = v[d + 32] * cc + v[d] * ss;
            }
            if (z == 0) {
#pragma unroll
                for (int j = 0; j < 64; j++) o[j] *= QSC_;
            }
        } else {
#pragma unroll
            for (int j = 0; j < 64; j++) o[j] = v[j];
        }
        if (!valid) {
#pragma unroll
            for (int j = 0; j < 64; j++) o[j] = 0.f;
        }
        int h = (col0 >> 6) + hh;
        size_t off = (((size_t)b * H_ + h) * T_ + t) * DH_;
#pragma unroll
        for (int j = 0; j < 64; j += 4) {
            ushort4 hv, lv;
            __nv_bfloat16 h0=__float2bfloat16_rn(o[j+0]), h1=__float2bfloat16_rn(o[j+1]);
            __nv_bfloat16 h2=__float2bfloat16_rn(o[j+2]), h3=__float2bfloat16_rn(o[j+3]);
            hv.x=__bfloat16_as_ushort(h0); hv.y=__bfloat16_as_ushort(h1);
            hv.z=__bfloat16_as_ushort(h2); hv.w=__bfloat16_as_ushort(h3);
            lv.x=__bfloat16_as_ushort(__float2bfloat16_rn(o[j+0]-__bfloat162float(h0)));
            lv.y=__bfloat16_as_ushort(__float2bfloat16_rn(o[j+1]-__bfloat162float(h1)));
            lv.z=__bfloat16_as_ushort(__float2bfloat16_rn(o[j+2]-__bfloat162float(h2)));
            lv.w=__bfloat16_as_ushort(__float2bfloat16_rn(o[j+3]-__bfloat162float(h3)));
            *(ushort4*)(dsth + off + j) = hv;
            *(ushort4*)(dstl + off + j) = lv;
        }
    }
}

// ---------------- out-proj GEMM: 128x64 tiles, grid 512 (R13-verified) -----------
#define OT_A_B_   (128*ROWB_)
#define OT_B_B_   (64*ROWB_)
#define OT_STG_   (2*OT_A_B_ + 2*OT_B_B_)
#define SMEM_OUT_ (2*OT_STG_)

__global__ void __launch_bounds__(256, 2) gemm_out64_kernel(
    const float* __restrict__ bo, float* __restrict__ Out,
    const int* __restrict__ nc)
{
    int bid  = blockIdx.x;
    int row0 = (bid >> 4) * 128;
    int col0 = (bid & 15) * 64;
    int b    = row0 >> 9;
    int t0b  = row0 & 511;
    int Nn   = nc[b];
    int tid  = threadIdx.x;

    if (t0b >= Nn) {
        float4 z4 = make_float4(0.f, 0.f, 0.f, 0.f);
        for (int i = tid; i < 128 * 16; i += 256) {
            int r = i >> 4, c4 = (i & 15) << 2;
            *(float4*)(Out + (size_t)(row0 + r) * DM_ + col0 + c4) = z4;
        }
        return;
    }

    extern __shared__ __align__(128) char smem[];
    uint32_t sbase = smem_u32(smem);

    int lane = tid & 31;
    int wid  = tid >> 5;
    int wm   = wid >> 2;
    int wn   = wid & 3;

    float acc[4][2][4];
#pragma unroll
    for (int i = 0; i < 4; i++)
#pragma unroll
        for (int j = 0; j < 2; j++)
#pragma unroll
            for (int q = 0; q < 4; q++) acc[i][j][q] = 0.f;

    int aRow = wm * 64 + (lane & 15);
    int aCol = (lane >> 4) << 3;
    int bRow = wn * 16 + (lane & 7);
    int bCol = ((lane >> 3) & 1) << 3;

#define OLOAD_STAGE(ii) do {                                                    \
        int _i = (ii);                                                          \
        int _s = _i & 1;                                                        \
        int _k0 = _i * KT_;                                                     \
        uint32_t _sd = sbase + _s * OT_STG_;                                    \
        _Pragma("unroll")                                                       \
        for (int _j = 0; _j < 6; _j++) {                                        \
            int _idx = tid + _j * 256;                                          \
            if (_idx < 1024) {                                                  \
                int _tile = _idx >> 9;                                          \
                int _r    = (_idx >> 2) & 127;                                  \
                int _c    = _idx & 3;                                           \
                const __nv_bfloat16* _gp = _tile ? g_at_lo : g_at_hi;           \
                cp_async16(_sd + _tile * OT_A_B_ + _r * ROWB_ + _c * 16,        \
                           _gp + (size_t)(row0 + _r) * DM_ + _k0 + _c * 8);     \
            } else {                                                            \
                int _q    = _idx - 1024;                                        \
                int _tile = _q >> 8;                                            \
                int _r    = (_q >> 2) & 63;                                     \
                int _c    = _q & 3;                                             \
                const __nv_bfloat16* _gp = (_tile ? g_wt_lo : g_wt_hi)          \
                                           + (size_t)3 * DM_ * DM_;             \
                cp_async16(_sd + 2 * OT_A_B_ + _tile * OT_B_B_                  \
                               + _r * ROWB_ + _c * 16,                          \
                           _gp + (size_t)(col0 + _r) * DM_ + _k0 + _c * 8);     \
            }                                                                   \
        }                                                                       \
        asm volatile("cp.async.commit_group;" ::: "memory");                    \
    } while (0)

    OLOAD_STAGE(0);
    for (int i = 0; i < NCHUNK_; i++) {
        if (i + 1 < NCHUNK_) {
            OLOAD_STAGE(i + 1);
            asm volatile("cp.async.wait_group 1;" ::: "memory");
        } else {
            asm volatile("cp.async.wait_group 0;" ::: "memory");
        }
        __syncthreads();

        uint32_t st = sbase + (i & 1) * OT_STG_;
        uint32_t stB = st + 2 * OT_A_B_;
#pragma unroll
        for (int kk = 0; kk < KT_; kk += 16) {
            uint32_t A[4][4], Bh[2][2], Bl[2][2];
#pragma unroll
            for (int fn = 0; fn < 2; fn++) {
                uint32_t off = (uint32_t)((bRow + fn * 8) * ROWB_ + (kk + bCol) * 2);
                ldm_x2(Bh[fn], stB + off);
                ldm_x2(Bl[fn], stB + OT_B_B_ + off);
            }
#pragma unroll
            for (int fm = 0; fm < 4; fm++) {
                uint32_t off = (uint32_t)((aRow + fm * 16) * ROWB_ + (kk + aCol) * 2);
                ldm_x4(A[fm], st + off);
            }
#pragma unroll
            for (int fm = 0; fm < 4; fm++)
#pragma unroll
                for (int fn = 0; fn < 2; fn++) {
                    mma16816(acc[fm][fn], A[fm], Bh[fn]);
                    mma16816(acc[fm][fn], A[fm], Bl[fn]);
                }
#pragma unroll
            for (int fm = 0; fm < 4; fm++) {
                uint32_t off = (uint32_t)((aRow + fm * 16) * ROWB_ + (kk + aCol) * 2);
                ldm_x4(A[fm], st + OT_A_B_ + off);
            }
#pragma unroll
            for (int fm = 0; fm < 4; fm++)
#pragma unroll
                for (int fn = 0; fn < 2; fn++)
                    mma16816(acc[fm][fn], A[fm], Bh[fn]);
        }
        __syncthreads();
    }
#undef OLOAD_STAGE

    float* Cs = (float*)smem;                  // [128][68]
#pragma unroll
    for (int fm = 0; fm < 4; fm++)
#pragma unroll
        for (int fn = 0; fn < 2; fn++) {
            int m = wm * 64 + fm * 16 + (lane >> 2);
            int n = wn * 16 + fn * 8 + ((lane & 3) << 1);
            *(float2*)&Cs[m * 68 + n]       = make_float2(acc[fm][fn][0], acc[fm][fn][1]);
            *(float2*)&Cs[(m + 8) * 68 + n] = make_float2(acc[fm][fn][2], acc[fm][fn][3]);
        }
    __syncthreads();

    {
        int r    = tid >> 1;
        int hh   = tid & 1;
        int m    = row0 + r;
        int t    = m & 511;
        bool valid = (t < Nn);
        const float* Cr = Cs + r * 68 + hh * 32;
        float* dst = Out + (size_t)m * DM_ + col0 + hh * 32;
        const float* bb = bo + col0 + hh * 32;
#pragma unroll
        for (int c = 0; c < 32; c += 4) {
            float4 o;
            o.x = valid ? Cr[c+0] + bb[c+0] : 0.f;
            o.y = valid ? Cr[c+1] + bb[c+1] : 0.f;
            o.z = valid ? Cr[c+2] + bb[c+2] : 0.f;
            o.w = valid ? Cr[c+3] + bb[c+3] : 0.f;
            *(float4*)(dst + c) = o;
        }
    }
}

// ---------------- Flash attention: 64-row q-tiles, 128 threads, 2 CTAs/SM --------
// smem: Qh @0 (9216), Ql @9216; stages @18432 + s*36864: kh,kl,vh,vl @ +9216 each
#define SMEM_ATTN_ 92160

__global__ void __launch_bounds__(128, 2) attn_mma_kernel(
    const int* __restrict__ plen, const int* __restrict__ nc)
{
    extern __shared__ __align__(128) char smem[];
    const uint32_t sbase = smem_u32(smem);

    int b = blockIdx.z, h = blockIdx.y, t0 = blockIdx.x * 64;
    int Nn = nc[b];
    if (t0 >= Nn) return;
    int Tp = plen[b]; Tp = Tp < 0 ? 0 : (Tp > P_ ? P_ : Tp);
    int Ltot   = Tp + Nn;
    int nPast  = (Tp + 63) >> 6;
    int newLen = Ltot - P_;
    int nNew   = newLen > 0 ? (newLen + 63) >> 6 : 0;
    int nblk   = nPast + nNew;
    int Tpad   = nPast << 6;
    int Z      = (P_ < Ltot ? P_ : Ltot) - Tpad; if (Z < 0) Z = 0;

    int tid = threadIdx.x, lane = tid & 31, wid = tid >> 5;   // wid 0..3
    size_t bh = (size_t)b * H_ + h;

    // ---- Q loads (64 rows, hi+lo = 1024 16B-chunks, 128 threads -> 8 iters) ----
    {
        const __nv_bfloat16* qh = g_qh + (bh * T_ + t0) * DH_;
        const __nv_bfloat16* ql = g_ql + (bh * T_ + t0) * DH_;
#pragma unroll
        for (int u = 0; u < 8; u++) {
            int idx = tid + u * 128;
            int arr = idx >> 9;
            int rem = idx & 511;
            int row = rem >> 3, c = rem & 7;
            const __nv_bfloat16* src = (arr ? ql : qh) + (size_t)row * DH_ + c * 8;
            cp_async16(sbase + arr * 9216 + row * 144 + c * 16, src);
        }
        asm volatile("cp.async.commit_group;" ::: "memory");
    }

    auto load_stage = [&](int i) {
        uint32_t SB = sbase + 18432 + (i & 1) * 36864;
        bool past = i < nPast;
        int j0 = past ? (i << 6) : (P_ + ((i - nPast) << 6));
        const __nv_bfloat16 *kh, *kl, *vh, *vl; size_t rb;
        if (past) { kh=g_pkh; kl=g_pkl; vh=g_pvh; vl=g_pvl; rb = bh * P_ + j0; }
        else      { kh=g_knh; kl=g_knl; vh=g_vnh; vl=g_vnl; rb = bh * T_ + (j0 - P_); }
#pragma unroll
        for (int u = 0; u < 16; u++) {
            int idx = tid + u * 128;
            int arr = idx >> 9;
            int rem = idx & 511;
            int row = rem >> 3, c = rem & 7;
            uint32_t dst = SB + arr * 9216 + row * 144 + c * 16;
            if (past && (j0 + row) >= Tp) {
                asm volatile("st.shared.v4.b32 [%0], {%1,%1,%1,%1};"
                             :: "r"(dst), "r"(0) : "memory");
            } else {
                const __nv_bfloat16* srcb = arr==0?kh:arr==1?kl:arr==2?vh:vl;
                cp_async16(dst, srcb + (rb + row) * DH_ + c * 8);
            }
        }
        asm volatile("cp.async.commit_group;" ::: "memory");
    };

    float m0 = -1e30f, m1 = -1e30f, l0 = 0.f, l1 = 0.f;
    float O[8][4];
#pragma unroll
    for (int nf = 0; nf < 8; nf++)
#pragma unroll
        for (int q = 0; q < 4; q++) O[nf][q] = 0.f;

    uint32_t Qh[4][4], Ql[4][4];

    if (nblk > 0) {
        load_stage(0);
        asm volatile("cp.async.wait_group 1;" ::: "memory");
        __syncthreads();
#pragma unroll
        for (int kk = 0; kk < 4; kk++) {
            uint32_t off = (uint32_t)((wid * 16 + (lane & 15)) * 144
                                      + (kk * 16 + ((lane >> 4) << 3)) * 2);
            ldm_x4(Qh[kk], sbase + off);
            ldm_x4(Ql[kk], sbase + 9216 + off);
        }
    } else {
        asm volatile("cp.async.wait_group 0;" ::: "memory");
    }

    for (int i = 0; i < nblk; i++) {
        __syncthreads();
        if (i + 1 < nblk) {
            load_stage(i + 1);
            asm volatile("cp.async.wait_group 1;" ::: "memory");
        } else {
            asm volatile("cp.async.wait_group 0;" ::: "memory");
        }
        __syncthreads();

        int j0 = (i < nPast) ? (i << 6) : (P_ + ((i - nPast) << 6));
        uint32_t SB = sbase + 18432 + (i & 1) * 36864;

        float S[8][4];
#pragma unroll
        for (int nf = 0; nf < 8; nf++)
#pragma unroll
            for (int q = 0; q < 4; q++) S[nf][q] = 0.f;
#pragma unroll
        for (int nf = 0; nf < 8; nf++) {
            uint32_t kfh[4][2], kfl[4][2];
#pragma unroll
            for (int kk = 0; kk < 4; kk++) {
                uint32_t off = (uint32_t)((nf * 8 + (lane & 7)) * 144
                                          + (kk * 16 + (((lane >> 3) & 1) << 3)) * 2);
                ldm_x2(kfh[kk], SB + off);
                ldm_x2(kfl[kk], SB + 9216 + off);
            }
#pragma unroll
            for (int kk = 0; kk < 4; kk++) {
                mma16816(S[nf], Qh[kk], kfh[kk]);
                mma16816(S[nf], Qh[kk], kfl[kk]);
                mma16816(S[nf], Ql[kk], kfh[kk]);
            }
        }

#pragma unroll
        for (int nf = 0; nf < 8; nf++) {
            int keyc = j0 + nf * 8 + ((lane & 3) << 1);
            if (keyc     >= Ltot) { S[nf][0] = -1e9f; S[nf][2] = -1e9f; }
            if (keyc + 1 >= Ltot) { S[nf][1] = -1e9f; S[nf][3] = -1e9f; }
        }

        float mx0 = -1e30f, mx1 = -1e30f;
#pragma unroll
        for (int nf = 0; nf < 8; nf++) {
            mx0 = fmaxf(mx0, fmaxf(S[nf][0], S[nf][1]));
            mx1 = fmaxf(mx1, fmaxf(S[nf][2], S[nf][3]));
        }
        mx0 = fmaxf(mx0, __shfl_xor_sync(0xffffffffu, mx0, 1));
        mx0 = fmaxf(mx0, __shfl_xor_sync(0xffffffffu, mx0, 2));
        mx1 = fmaxf(mx1, __shfl_xor_sync(0xffffffffu, mx1, 1));
        mx1 = fmaxf(mx1, __shfl_xor_sync(0xffffffffu, mx1, 2));
        float nm0 = fmaxf(m0, mx0), nm1 = fmaxf(m1, mx1);
        float a0 = ex2f(m0 - nm0), a1 = ex2f(m1 - nm1);
        m0 = nm0; m1 = nm1;
        float rs0 = 0.f, rs1 = 0.f;
#pragma unroll
        for (int nf = 0; nf < 8; nf++) {
            S[nf][0] = ex2f(S[nf][0] - nm0);
            S[nf][1] = ex2f(S[nf][1] - nm0);
            S[nf][2] = ex2f(S[nf][2] - nm1);
            S[nf][3] = ex2f(S[nf][3] - nm1);
            rs0 += S[nf][0] + S[nf][1];
            rs1 += S[nf][2] + S[nf][3];
        }
        rs0 += __shfl_xor_sync(0xffffffffu, rs0, 1);
        rs0 += __shfl_xor_sync(0xffffffffu, rs0, 2);
        rs1 += __shfl_xor_sync(0xffffffffu, rs1, 1);
        rs1 += __shfl_xor_sync(0xffffffffu, rs1, 2);
        l0 = l0 * a0 + rs0;
        l1 = l1 * a1 + rs1;
#pragma unroll
        for (int nf = 0; nf < 8; nf++) {
            O[nf][0] *= a0; O[nf][1] *= a0;
            O[nf][2] *= a1; O[nf][3] *= a1;
        }

        uint32_t Ph[4][4], Pl[4][4];
#pragma unroll
        for (int kk = 0; kk < 4; kk++) {
            float p0 = S[2*kk][0],   p1 = S[2*kk][1],   p2 = S[2*kk][2],   p3 = S[2*kk][3];
            float q0 = S[2*kk+1][0], q1 = S[2*kk+1][1], q2 = S[2*kk+1][2], q3 = S[2*kk+1][3];
            uint32_t u;
            u = packbf(p0, p1); Ph[kk][0] = u; Pl[kk][0] = packbf(p0 - bflo(u), p1 - bfhi(u));
            u = packbf(p2, p3); Ph[kk][1] = u; Pl[kk][1] = packbf(p2 - bflo(u), p3 - bfhi(u));
            u = packbf(q0, q1); Ph[kk][2] = u; Pl[kk][2] = packbf(q0 - bflo(u), q1 - bfhi(u));
            u = packbf(q2, q3); Ph[kk][3] = u; Pl[kk][3] = packbf(q2 - bflo(u), q3 - bfhi(u));
        }

#pragma unroll
        for (int nf = 0; nf < 8; nf++) {
            uint32_t vfh[4][2], vfl[4][2];
#pragma unroll
            for (int kk = 0; kk < 4; kk++) {
                uint32_t off = (uint32_t)((kk * 16 + (lane & 15)) * 144 + nf * 16);
                ldm_x2t(vfh[kk], SB + 18432 + off);
                ldm_x2t(vfl[kk], SB + 27648 + off);
            }
#pragma unroll
            for (int kk = 0; kk < 4; kk++) {
                mma16816(O[nf], Ph[kk], vfh[kk]);
                mma16816(O[nf], Ph[kk], vfl[kk]);
                mma16816(O[nf], Pl[kk], vfh[kk]);
            }
        }
    }

    if (Z > 0) {
        float nm0 = fmaxf(m0, 0.f), nm1 = fmaxf(m1, 0.f);
        float a0 = ex2f(m0 - nm0), a1 = ex2f(m1 - nm1);
        l0 = l0 * a0 + (float)Z * ex2f(-nm0);
        l1 = l1 * a1 + (float)Z * ex2f(-nm1);
#pragma unroll
        for (int nf = 0; nf < 8; nf++) {
            O[nf][0] *= a0; O[nf][1] *= a0;
            O[nf][2] *= a1; O[nf][3] *= a1;
        }
    }

    float inv0 = 1.f / l0, inv1 = 1.f / l1;
    float* Os = (float*)smem;          // [64][68] = 17408 B, fits in Q region+stage0
    __syncthreads();
    {
        int r0 = wid * 16 + (lane >> 2);
        int cb = (lane & 3) << 1;
#pragma unroll
        for (int nf = 0; nf < 8; nf++) {
            *(float2*)&Os[r0 * 68 + nf * 8 + cb] =
                make_float2(O[nf][0] * inv0, O[nf][1] * inv0);
            *(float2*)&Os[(r0 + 8) * 68 + nf * 8 + cb] =
                make_float2(O[nf][2] * inv1, O[nf][3] * inv1);
        }
    }
    __syncthreads();
    {
        int r = tid >> 1;              // 0..63
        int half = (tid & 1) * 32;
        int t = t0 + r;
        size_t orow = ((size_t)b * T_ + t) * DM_ + h * DH_ + half;
        const float* Or = Os + r * 68 + half;
#pragma unroll
        for (int j = 0; j < 32; j += 4) {
            float v0 = Or[j], v1 = Or[j+1], v2 = Or[j+2], v3 = Or[j+3];
            __nv_bfloat16 h0=__float2bfloat16_rn(v0), h1=__float2bfloat16_rn(v1);
            __nv_bfloat16 h2=__float2bfloat16_rn(v2), h3=__float2bfloat16_rn(v3);
            ushort4 hv, lv;
            hv.x=__bfloat16_as_ushort(h0); hv.y=__bfloat16_as_ushort(h1);
            hv.z=__bfloat16_as_ushort(h2); hv.w=__bfloat16_as_ushort(h3);
            lv.x=__bfloat16_as_ushort(__float2bfloat16_rn(v0-__bfloat162float(h0)));
            lv.y=__bfloat16_as_ushort(__float2bfloat16_rn(v1-__bfloat162float(h1)));
            lv.z=__bfloat16_as_ushort(__float2bfloat16_rn(v2-__bfloat162float(h2)));
            lv.w=__bfloat16_as_ushort(__float2bfloat16_rn(v3-__bfloat162float(h3)));
            *(ushort4*)(g_at_hi + orow + j) = hv;
            *(ushort4*)(g_at_lo + orow + j) = lv;
        }
    }
}

// ---------------- launch ----------------
extern "C" void kernel_launch(void* const* d_in, const int* in_sizes, int n_in,
                              void* d_out, int out_size)
{
    const float* x   = (const float*)d_in[0];
    const float* rc  = (const float*)d_in[1];
    const float* rs  = (const float*)d_in[2];
    const float* pk  = (const float*)d_in[3];
    const float* pv  = (const float*)d_in[4];
    const int*   pl  = (const int*)  d_in[5];
    const int*   nc  = (const int*)  d_in[7];
    const float* Wq  = (const float*)d_in[8];
    const float* bq  = (const float*)d_in[9];
    const float* Wk  = (const float*)d_in[10];
    const float* bk  = (const float*)d_in[11];
    const float* Wv  = (const float*)d_in[12];
    const float* bv  = (const float*)d_in[13];
    const float* Wo  = (const float*)d_in[14];
    const float* bo  = (const float*)d_in[15];
    float* out = (float*)d_out;

    cudaFuncSetAttribute(mma_gemm_kernel,
                         cudaFuncAttributeMaxDynamicSharedMemorySize, SMEM_GEMM_);
    cudaFuncSetAttribute(gemm_out64_kernel,
                         cudaFuncAttributeMaxDynamicSharedMemorySize, SMEM_OUT_);
    cudaFuncSetAttribute(attn_mma_kernel,
                         cudaFuncAttributeMaxDynamicSharedMemorySize, SMEM_ATTN_);

    fused_prep_kernel<<<PREP_TOTAL_BLKS_, 256>>>(x, Wq, Wk, Wv, Wo, pk, pv, pl);
    mma_gemm_kernel<<<dim3(8, 32, 3), 256, SMEM_GEMM_>>>(rc, rs, bq, bk, bv, nc);
    attn_mma_kernel<<<dim3(T_/64, H_, B_), 128, SMEM_ATTN_>>>(pl, nc);
    gemm_out64_kernel<<<512, 256, SMEM_OUT_>>>(bo, out, nc);
}

// round 17
// speedup vs baseline: 1.0399x; 1.0108x over previous
#include <cuda_runtime.h>
#include <cuda_bf16.h>
#include <math.h>
#include <stdint.h>

#define B_   8
#define T_   512
#define DM_  1024
#define H_   16
#define DH_  64
#define P_   3584
#define BT_  (B_*T_)       // 4096
#define BHTD_ (B_*H_*T_*DH_)   // 4194304
#define BHPD_ (B_*H_*P_*DH_)   // 29360128
#define QSC_ 0.18033688011112042f   // 0.125 * log2(e): scores in log2 units

// ---------------- scratch (device globals; zero-initialized at load) ----------------
__device__ __nv_bfloat16 g_x_hi[BT_*DM_];
__device__ __nv_bfloat16 g_x_lo[BT_*DM_];
__device__ __nv_bfloat16 g_at_hi[BT_*DM_];
__device__ __nv_bfloat16 g_at_lo[BT_*DM_];
__device__ __nv_bfloat16 g_wt_hi[4*DM_*DM_];
__device__ __nv_bfloat16 g_wt_lo[4*DM_*DM_];
__device__ __nv_bfloat16 g_qh [BHTD_+64*DH_];
__device__ __nv_bfloat16 g_ql [BHTD_+64*DH_];
__device__ __nv_bfloat16 g_knh[BHTD_+64*DH_];
__device__ __nv_bfloat16 g_knl[BHTD_+64*DH_];
__device__ __nv_bfloat16 g_vnh[BHTD_+64*DH_];
__device__ __nv_bfloat16 g_vnl[BHTD_+64*DH_];
__device__ __nv_bfloat16 g_pkh[BHPD_];
__device__ __nv_bfloat16 g_pkl[BHPD_];
__device__ __nv_bfloat16 g_pvh[BHPD_];
__device__ __nv_bfloat16 g_pvl[BHPD_];

// ---------------- helpers ----------------
__device__ __forceinline__ uint32_t smem_u32(const void* p) {
    uint32_t a;
    asm("{ .reg .u64 t; cvta.to.shared.u64 t, %1; cvt.u32.u64 %0, t; }" : "=r"(a) : "l"(p));
    return a;
}
__device__ __forceinline__ void ldm_x4(uint32_t* r, uint32_t addr) {
    asm volatile("ldmatrix.sync.aligned.m8n8.x4.shared.b16 {%0,%1,%2,%3}, [%4];"
        : "=r"(r[0]), "=r"(r[1]), "=r"(r[2]), "=r"(r[3]) : "r"(addr));
}
__device__ __forceinline__ void ldm_x2(uint32_t* r, uint32_t addr) {
    asm volatile("ldmatrix.sync.aligned.m8n8.x2.shared.b16 {%0,%1}, [%2];"
        : "=r"(r[0]), "=r"(r[1]) : "r"(addr));
}
__device__ __forceinline__ void ldm_x2t(uint32_t* r, uint32_t addr) {
    asm volatile("ldmatrix.sync.aligned.m8n8.x2.trans.shared.b16 {%0,%1}, [%2];"
        : "=r"(r[0]), "=r"(r[1]) : "r"(addr));
}
__device__ __forceinline__ void mma16816(float* d, const uint32_t* a, const uint32_t* b) {
    asm volatile("mma.sync.aligned.m16n8k16.row.col.f32.bf16.bf16.f32 "
        "{%0,%1,%2,%3}, {%4,%5,%6,%7}, {%8,%9}, {%0,%1,%2,%3};"
        : "+f"(d[0]), "+f"(d[1]), "+f"(d[2]), "+f"(d[3])
        : "r"(a[0]), "r"(a[1]), "r"(a[2]), "r"(a[3]), "r"(b[0]), "r"(b[1]));
}
__device__ __forceinline__ void cp_async16(uint32_t dst, const void* src) {
    asm volatile("cp.async.cg.shared.global [%0], [%1], 16;" :: "r"(dst), "l"(src));
}
__device__ __forceinline__ float ex2f(float x) {
    float r; asm("ex2.approx.ftz.f32 %0, %1;" : "=f"(r) : "f"(x)); return r;
}
__device__ __forceinline__ uint32_t packbf(float lo, float hi) {
    uint32_t r; asm("cvt.rn.bf16x2.f32 %0, %1, %2;" : "=r"(r) : "f"(hi), "f"(lo)); return r;
}
__device__ __forceinline__ float bflo(uint32_t u){ return __uint_as_float(u << 16); }
__device__ __forceinline__ float bfhi(uint32_t u){ return __uint_as_float(u & 0xffff0000u); }

// ---------------- fused prep: conv_split + prep_w + prep_past (R11-verified) -----
#define PREP_CONV_BLKS_ 4096
#define PREP_W_BLKS_    4096
#define PREP_PAST_BLKS_ 28672
#define PREP_TOTAL_BLKS_ (PREP_CONV_BLKS_ + PREP_W_BLKS_ + PREP_PAST_BLKS_)

__global__ __launch_bounds__(256) void fused_prep_kernel(
    const float* __restrict__ xsrc,
    const float* __restrict__ Wq, const float* __restrict__ Wk,
    const float* __restrict__ Wv, const float* __restrict__ Wo,
    const float* __restrict__ pk, const float* __restrict__ pv,
    const int* __restrict__ plen)
{
    __shared__ float ts[32][33];
    int bid = blockIdx.x;
    int tid = threadIdx.x;

    if (bid < PREP_CONV_BLKS_) {
        int i4 = bid * 256 + tid;
        float4 v = ((const float4*)xsrc)[i4];
        __nv_bfloat16 h0 = __float2bfloat16_rn(v.x), h1 = __float2bfloat16_rn(v.y);
        __nv_bfloat16 h2 = __float2bfloat16_rn(v.z), h3 = __float2bfloat16_rn(v.w);
        ushort4 ho, lw;
        ho.x = __bfloat16_as_ushort(h0); ho.y = __bfloat16_as_ushort(h1);
        ho.z = __bfloat16_as_ushort(h2); ho.w = __bfloat16_as_ushort(h3);
        lw.x = __bfloat16_as_ushort(__float2bfloat16_rn(v.x - __bfloat162float(h0)));
        lw.y = __bfloat16_as_ushort(__float2bfloat16_rn(v.y - __bfloat162float(h1)));
        lw.z = __bfloat16_as_ushort(__float2bfloat16_rn(v.z - __bfloat162float(h2)));
        lw.w = __bfloat16_as_ushort(__float2bfloat16_rn(v.w - __bfloat162float(h3)));
        ((ushort4*)g_x_hi)[i4] = ho;
        ((ushort4*)g_x_lo)[i4] = lw;
    } else if (bid < PREP_CONV_BLKS_ + PREP_W_BLKS_) {
        int j  = bid - PREP_CONV_BLKS_;
        int zz = j >> 10;
        int r  = j & 1023;
        int n0 = (r & 31) * 32;
        int k0 = (r >> 5) * 32;
        const float* W = (zz == 0) ? Wq : (zz == 1) ? Wk : (zz == 2) ? Wv : Wo;
        size_t base = (size_t)zz * DM_ * DM_;
        int tx = tid & 31, ty8 = tid >> 5;
        for (int i = ty8; i < 32; i += 8)
            ts[i][tx] = W[(size_t)(k0 + i) * DM_ + n0 + tx];
        __syncthreads();
        for (int i = ty8; i < 32; i += 8) {
            float v = ts[tx][i];
            __nv_bfloat16 h = __float2bfloat16_rn(v);
            __nv_bfloat16 l = __float2bfloat16_rn(v - __bfloat162float(h));
            size_t off = base + (size_t)(n0 + i) * DM_ + k0 + tx;
            g_wt_hi[off] = h;
            g_wt_lo[off] = l;
        }
    } else {
        int j  = bid - PREP_CONV_BLKS_ - PREP_W_BLKS_;
        int xb = j % 224;
        int bh = j / 224;
        int b  = bh >> 4;
        int Tp = plen[b]; Tp = Tp < 0 ? 0 : (Tp > P_ ? P_ : Tp);
        int i4 = xb * 256 + tid;
        int key = i4 >> 4;
        if (key >= Tp) return;
        size_t off = (size_t)bh * (P_*DH_) + (size_t)i4 * 4;
        float4 kv = *(const float4*)(pk + off);
        float4 vv = *(const float4*)(pv + off);
#define SPLIT4(V, HI, LO) do {                                                  \
        __nv_bfloat16 h0=__float2bfloat16_rn(V.x), h1=__float2bfloat16_rn(V.y); \
        __nv_bfloat16 h2=__float2bfloat16_rn(V.z), h3=__float2bfloat16_rn(V.w); \
        ushort4 hv, lv;                                                          \
        hv.x=__bfloat16_as_ushort(h0); hv.y=__bfloat16_as_ushort(h1);            \
        hv.z=__bfloat16_as_ushort(h2); hv.w=__bfloat16_as_ushort(h3);            \
        lv.x=__bfloat16_as_ushort(__float2bfloat16_rn(V.x-__bfloat162float(h0)));\
        lv.y=__bfloat16_as_ushort(__float2bfloat16_rn(V.y-__bfloat162float(h1)));\
        lv.z=__bfloat16_as_ushort(__float2bfloat16_rn(V.z-__bfloat162float(h2)));\
        lv.w=__bfloat16_as_ushort(__float2bfloat16_rn(V.w-__bfloat162float(h3)));\
        *(ushort4*)(HI + off) = hv; *(ushort4*)(LO + off) = lv;                  \
    } while(0)
        SPLIT4(kv, g_pkh, g_pkl);
        SPLIT4(vv, g_pvh, g_pvl);
#undef SPLIT4
    }
}

// ---------------- mma.sync QKV GEMM: single-A-read inner loop --------------------
#define KT_          32
#define NCHUNK_      (DM_/KT_)
#define ROWB_        80
#define TILE_B_      (128*ROWB_)
#define STAGE_B_     (4*TILE_B_)
#define SMEM_GEMM_   (2*STAGE_B_)

__global__ void __launch_bounds__(256, 2) mma_gemm_kernel(
    const float* __restrict__ rcos, const float* __restrict__ rsin,
    const float* __restrict__ bq, const float* __restrict__ bk,
    const float* __restrict__ bv, const int* __restrict__ nc)
{
    int z    = blockIdx.z;
    int row0 = blockIdx.y * 128;
    int col0 = blockIdx.x * 128;
    int b    = row0 >> 9;
    int t0b  = row0 & 511;
    int Nn   = nc[b];
    int tid  = threadIdx.x;

    if (t0b >= Nn) return;

    const __nv_bfloat16* Ahi = g_x_hi;
    const __nv_bfloat16* Alo = g_x_lo;
    const __nv_bfloat16* Bhi = g_wt_hi + (size_t)z * DM_ * DM_;
    const __nv_bfloat16* Blo = g_wt_lo + (size_t)z * DM_ * DM_;

    extern __shared__ __align__(128) char smem[];
    uint32_t sbase = smem_u32(smem);

    int lane = tid & 31;
    int wid  = tid >> 5;
    int wm   = wid >> 2;
    int wn   = wid & 3;

    float acc[4][4][4];
#pragma unroll
    for (int i = 0; i < 4; i++)
#pragma unroll
        for (int j = 0; j < 4; j++)
#pragma unroll
            for (int q = 0; q < 4; q++) acc[i][j][q] = 0.f;

    int aRow = wm * 64 + (lane & 15);
    int aCol = (lane >> 4) << 3;
    int bRow = wn * 32 + (lane & 7);
    int bCol = ((lane >> 3) & 1) << 3;

#define LOAD_STAGE(ii) do {                                                     \
        int _i = (ii);                                                          \
        int _s = _i & 1;                                                        \
        int _k0 = _i * KT_;                                                     \
        uint32_t _sd = sbase + _s * STAGE_B_;                                   \
        _Pragma("unroll")                                                       \
        for (int _j = 0; _j < 8; _j++) {                                        \
            int _idx  = tid + _j * 256;                                         \
            int _tile = _idx >> 9;                                              \
            int _r    = (_idx >> 2) & 127;                                      \
            int _c    = _idx & 3;                                               \
            const __nv_bfloat16* _gp =                                          \
                (_tile == 0) ? Ahi : (_tile == 1) ? Alo :                       \
                (_tile == 2) ? Bhi : Blo;                                       \
            int _grow = (_tile < 2) ? (row0 + _r) : (col0 + _r);                \
            cp_async16(_sd + _tile * TILE_B_ + _r * ROWB_ + _c * 16,            \
                       _gp + (size_t)_grow * DM_ + _k0 + _c * 8);               \
        }                                                                       \
        asm volatile("cp.async.commit_group;" ::: "memory");                    \
    } while (0)

    LOAD_STAGE(0);
    for (int i = 0; i < NCHUNK_; i++) {
        if (i + 1 < NCHUNK_) {
            LOAD_STAGE(i + 1);
            asm volatile("cp.async.wait_group 1;" ::: "memory");
        } else {
            asm volatile("cp.async.wait_group 0;" ::: "memory");
        }
        __syncthreads();

        uint32_t st = sbase + (i & 1) * STAGE_B_;
#pragma unroll
        for (int kk = 0; kk < KT_; kk += 16) {
            uint32_t Bh[4][2], Bl[4][2];
#pragma unroll
            for (int fn = 0; fn < 4; fn++) {
                uint32_t off = (uint32_t)((bRow + fn * 8) * ROWB_ + (kk + bCol) * 2);
                ldm_x2(Bh[fn], st + 2 * TILE_B_ + off);
                ldm_x2(Bl[fn], st + 3 * TILE_B_ + off);
            }
#pragma unroll
            for (int fm = 0; fm < 4; fm++) {
                uint32_t Ah4[4], Al4[4];
                uint32_t off = (uint32_t)((aRow + fm * 16) * ROWB_ + (kk + aCol) * 2);
                ldm_x4(Ah4, st + 0 * TILE_B_ + off);
                ldm_x4(Al4, st + 1 * TILE_B_ + off);
#pragma unroll
                for (int fn = 0; fn < 4; fn++) mma16816(acc[fm][fn], Ah4, Bh[fn]);
#pragma unroll
                for (int fn = 0; fn < 4; fn++) mma16816(acc[fm][fn], Ah4, Bl[fn]);
#pragma unroll
                for (int fn = 0; fn < 4; fn++) mma16816(acc[fm][fn], Al4, Bh[fn]);
            }
        }
        __syncthreads();
    }
#undef LOAD_STAGE

    float* Cs = (float*)smem;                  // [128][132]
#pragma unroll
    for (int fm = 0; fm < 4; fm++)
#pragma unroll
        for (int fn = 0; fn < 4; fn++) {
            int m = wm * 64 + fm * 16 + (lane >> 2);
            int n = wn * 32 + fn * 8 + ((lane & 3) << 1);
            *(float2*)&Cs[m * 132 + n]       = make_float2(acc[fm][fn][0], acc[fm][fn][1]);
            *(float2*)&Cs[(m + 8) * 132 + n] = make_float2(acc[fm][fn][2], acc[fm][fn][3]);
        }
    __syncthreads();

    {
        int r    = tid >> 1;
        int hh   = tid & 1;
        int m    = row0 + r;
        int t    = m & 511;
        bool valid = (t < Nn);
        const float* Cr = Cs + r * 132 + hh * 64;
        const float* bias = ((z == 0) ? bq : (z == 1) ? bk : bv) + col0 + hh * 64;
        __nv_bfloat16 *dsth, *dstl;
        if (z == 0)      { dsth = g_qh;  dstl = g_ql;  }
        else if (z == 1) { dsth = g_knh; dstl = g_knl; }
        else             { dsth = g_vnh; dstl = g_vnl; }
        float v[64], o[64];
#pragma unroll
        for (int j = 0; j < 64; j++) v[j] = Cr[j] + bias[j];
        if (z < 2) {
#pragma unroll
            for (int d = 0; d < 32; d++) {
                float cc = rcos[(t << 6) + d];
                float ss = rsin[(t << 6) + d];
                o[d]      = v[d] * cc - v[d + 32] * ss;
                o[d + 32] = v[d + 32] * cc + v[d] * ss;
            }
            if (z == 0) {
#pragma unroll
                for (int j = 0; j < 64; j++) o[j] *= QSC_;
            }
        } else {
#pragma unroll
            for (int j = 0; j < 64; j++) o[j] = v[j];
        }
        if (!valid) {
#pragma unroll
            for (int j = 0; j < 64; j++) o[j] = 0.f;
        }
        int h = (col0 >> 6) + hh;
        size_t off = (((size_t)b * H_ + h) * T_ + t) * DH_;
#pragma unroll
        for (int j = 0; j < 64; j += 4) {
            ushort4 hv, lv;
            __nv_bfloat16 h0=__float2bfloat16_rn(o[j+0]), h1=__float2bfloat16_rn(o[j+1]);
            __nv_bfloat16 h2=__float2bfloat16_rn(o[j+2]), h3=__float2bfloat16_rn(o[j+3]);
            hv.x=__bfloat16_as_ushort(h0); hv.y=__bfloat16_as_ushort(h1);
            hv.z=__bfloat16_as_ushort(h2); hv.w=__bfloat16_as_ushort(h3);
            lv.x=__bfloat16_as_ushort(__float2bfloat16_rn(o[j+0]-__bfloat162float(h0)));
            lv.y=__bfloat16_as_ushort(__float2bfloat16_rn(o[j+1]-__bfloat162float(h1)));
            lv.z=__bfloat16_as_ushort(__float2bfloat16_rn(o[j+2]-__bfloat162float(h2)));
            lv.w=__bfloat16_as_ushort(__float2bfloat16_rn(o[j+3]-__bfloat162float(h3)));
            *(ushort4*)(dsth + off + j) = hv;
            *(ushort4*)(dstl + off + j) = lv;
        }
    }
}

// ---------------- out-proj GEMM: 128x64 tiles, single-A-read ---------------------
#define OT_A_B_   (128*ROWB_)
#define OT_B_B_   (64*ROWB_)
#define OT_STG_   (2*OT_A_B_ + 2*OT_B_B_)
#define SMEM_OUT_ (2*OT_STG_)

__global__ void __launch_bounds__(256, 2) gemm_out64_kernel(
    const float* __restrict__ bo, float* __restrict__ Out,
    const int* __restrict__ nc)
{
    int bid  = blockIdx.x;
    int row0 = (bid >> 4) * 128;
    int col0 = (bid & 15) * 64;
    int b    = row0 >> 9;
    int t0b  = row0 & 511;
    int Nn   = nc[b];
    int tid  = threadIdx.x;

    if (t0b >= Nn) {
        float4 z4 = make_float4(0.f, 0.f, 0.f, 0.f);
        for (int i = tid; i < 128 * 16; i += 256) {
            int r = i >> 4, c4 = (i & 15) << 2;
            *(float4*)(Out + (size_t)(row0 + r) * DM_ + col0 + c4) = z4;
        }
        return;
    }

    extern __shared__ __align__(128) char smem[];
    uint32_t sbase = smem_u32(smem);

    int lane = tid & 31;
    int wid  = tid >> 5;
    int wm   = wid >> 2;
    int wn   = wid & 3;

    float acc[4][2][4];
#pragma unroll
    for (int i = 0; i < 4; i++)
#pragma unroll
        for (int j = 0; j < 2; j++)
#pragma unroll
            for (int q = 0; q < 4; q++) acc[i][j][q] = 0.f;

    int aRow = wm * 64 + (lane & 15);
    int aCol = (lane >> 4) << 3;
    int bRow = wn * 16 + (lane & 7);
    int bCol = ((lane >> 3) & 1) << 3;

#define OLOAD_STAGE(ii) do {                                                    \
        int _i = (ii);                                                          \
        int _s = _i & 1;                                                        \
        int _k0 = _i * KT_;                                                     \
        uint32_t _sd = sbase + _s * OT_STG_;                                    \
        _Pragma("unroll")                                                       \
        for (int _j = 0; _j < 6; _j++) {                                        \
            int _idx = tid + _j * 256;                                          \
            if (_idx < 1024) {                                                  \
                int _tile = _idx >> 9;                                          \
                int _r    = (_idx >> 2) & 127;                                  \
                int _c    = _idx & 3;                                           \
                const __nv_bfloat16* _gp = _tile ? g_at_lo : g_at_hi;           \
                cp_async16(_sd + _tile * OT_A_B_ + _r * ROWB_ + _c * 16,        \
                           _gp + (size_t)(row0 + _r) * DM_ + _k0 + _c * 8);     \
            } else {                                                            \
                int _q    = _idx - 1024;                                        \
                int _tile = _q >> 8;                                            \
                int _r    = (_q >> 2) & 63;                                     \
                int _c    = _q & 3;                                             \
                const __nv_bfloat16* _gp = (_tile ? g_wt_lo : g_wt_hi)          \
                                           + (size_t)3 * DM_ * DM_;             \
                cp_async16(_sd + 2 * OT_A_B_ + _tile * OT_B_B_                  \
                               + _r * ROWB_ + _c * 16,                          \
                           _gp + (size_t)(col0 + _r) * DM_ + _k0 + _c * 8);     \
            }                                                                   \
        }                                                                       \
        asm volatile("cp.async.commit_group;" ::: "memory");                    \
    } while (0)

    OLOAD_STAGE(0);
    for (int i = 0; i < NCHUNK_; i++) {
        if (i + 1 < NCHUNK_) {
            OLOAD_STAGE(i + 1);
            asm volatile("cp.async.wait_group 1;" ::: "memory");
        } else {
            asm volatile("cp.async.wait_group 0;" ::: "memory");
        }
        __syncthreads();

        uint32_t st = sbase + (i & 1) * OT_STG_;
        uint32_t stB = st + 2 * OT_A_B_;
#pragma unroll
        for (int kk = 0; kk < KT_; kk += 16) {
            uint32_t Bh[2][2], Bl[2][2];
#pragma unroll
            for (int fn = 0; fn < 2; fn++) {
                uint32_t off = (uint32_t)((bRow + fn * 8) * ROWB_ + (kk + bCol) * 2);
                ldm_x2(Bh[fn], stB + off);
                ldm_x2(Bl[fn], stB + OT_B_B_ + off);
            }
#pragma unroll
            for (int fm = 0; fm < 4; fm++) {
                uint32_t Ah4[4], Al4[4];
                uint32_t off = (uint32_t)((aRow + fm * 16) * ROWB_ + (kk + aCol) * 2);
                ldm_x4(Ah4, st + off);
                ldm_x4(Al4, st + OT_A_B_ + off);
#pragma unroll
                for (int fn = 0; fn < 2; fn++) mma16816(acc[fm][fn], Ah4, Bh[fn]);
#pragma unroll
                for (int fn = 0; fn < 2; fn++) mma16816(acc[fm][fn], Ah4, Bl[fn]);
#pragma unroll
                for (int fn = 0; fn < 2; fn++) mma16816(acc[fm][fn], Al4, Bh[fn]);
            }
        }
        __syncthreads();
    }
#undef OLOAD_STAGE

    float* Cs = (float*)smem;                  // [128][68]
#pragma unroll
    for (int fm = 0; fm < 4; fm++)
#pragma unroll
        for (int fn = 0; fn < 2; fn++) {
            int m = wm * 64 + fm * 16 + (lane >> 2);
            int n = wn * 16 + fn * 8 + ((lane & 3) << 1);
            *(float2*)&Cs[m * 68 + n]       = make_float2(acc[fm][fn][0], acc[fm][fn][1]);
            *(float2*)&Cs[(m + 8) * 68 + n] = make_float2(acc[fm][fn][2], acc[fm][fn][3]);
        }
    __syncthreads();

    {
        int r    = tid >> 1;
        int hh   = tid & 1;
        int m    = row0 + r;
        int t    = m & 511;
        bool valid = (t < Nn);
        const float* Cr = Cs + r * 68 + hh * 32;
        float* dst = Out + (size_t)m * DM_ + col0 + hh * 32;
        const float* bb = bo + col0 + hh * 32;
#pragma unroll
        for (int c = 0; c < 32; c += 4) {
            float4 o;
            o.x = valid ? Cr[c+0] + bb[c+0] : 0.f;
            o.y = valid ? Cr[c+1] + bb[c+1] : 0.f;
            o.z = valid ? Cr[c+2] + bb[c+2] : 0.f;
            o.w = valid ? Cr[c+3] + bb[c+3] : 0.f;
            *(float4*)(dst + c) = o;
        }
    }
}

// ---------------- Flash attention: 64-row q-tiles, 128 threads (R16-verified) ----
#define SMEM_ATTN_ 92160

__global__ void __launch_bounds__(128, 2) attn_mma_kernel(
    const int* __restrict__ plen, const int* __restrict__ nc)
{
    extern __shared__ __align__(128) char smem[];
    const uint32_t sbase = smem_u32(smem);

    int b = blockIdx.z, h = blockIdx.y, t0 = blockIdx.x * 64;
    int Nn = nc[b];
    if (t0 >= Nn) return;
    int Tp = plen[b]; Tp = Tp < 0 ? 0 : (Tp > P_ ? P_ : Tp);
    int Ltot   = Tp + Nn;
    int nPast  = (Tp + 63) >> 6;
    int newLen = Ltot - P_;
    int nNew   = newLen > 0 ? (newLen + 63) >> 6 : 0;
    int nblk   = nPast + nNew;
    int Tpad   = nPast << 6;
    int Z      = (P_ < Ltot ? P_ : Ltot) - Tpad; if (Z < 0) Z = 0;

    int tid = threadIdx.x, lane = tid & 31, wid = tid >> 5;
    size_t bh = (size_t)b * H_ + h;

    {
        const __nv_bfloat16* qh = g_qh + (bh * T_ + t0) * DH_;
        const __nv_bfloat16* ql = g_ql + (bh * T_ + t0) * DH_;
#pragma unroll
        for (int u = 0; u < 8; u++) {
            int idx = tid + u * 128;
            int arr = idx >> 9;
            int rem = idx & 511;
            int row = rem >> 3, c = rem & 7;
            const __nv_bfloat16* src = (arr ? ql : qh) + (size_t)row * DH_ + c * 8;
            cp_async16(sbase + arr * 9216 + row * 144 + c * 16, src);
        }
        asm volatile("cp.async.commit_group;" ::: "memory");
    }

    auto load_stage = [&](int i) {
        uint32_t SB = sbase + 18432 + (i & 1) * 36864;
        bool past = i < nPast;
        int j0 = past ? (i << 6) : (P_ + ((i - nPast) << 6));
        const __nv_bfloat16 *kh, *kl, *vh, *vl; size_t rb;
        if (past) { kh=g_pkh; kl=g_pkl; vh=g_pvh; vl=g_pvl; rb = bh * P_ + j0; }
        else      { kh=g_knh; kl=g_knl; vh=g_vnh; vl=g_vnl; rb = bh * T_ + (j0 - P_); }
#pragma unroll
        for (int u = 0; u < 16; u++) {
            int idx = tid + u * 128;
            int arr = idx >> 9;
            int rem = idx & 511;
            int row = rem >> 3, c = rem & 7;
            uint32_t dst = SB + arr * 9216 + row * 144 + c * 16;
            if (past && (j0 + row) >= Tp) {
                asm volatile("st.shared.v4.b32 [%0], {%1,%1,%1,%1};"
                             :: "r"(dst), "r"(0) : "memory");
            } else {
                const __nv_bfloat16* srcb = arr==0?kh:arr==1?kl:arr==2?vh:vl;
                cp_async16(dst, srcb + (rb + row) * DH_ + c * 8);
            }
        }
        asm volatile("cp.async.commit_group;" ::: "memory");
    };

    float m0 = -1e30f, m1 = -1e30f, l0 = 0.f, l1 = 0.f;
    float O[8][4];
#pragma unroll
    for (int nf = 0; nf < 8; nf++)
#pragma unroll
        for (int q = 0; q < 4; q++) O[nf][q] = 0.f;

    uint32_t Qh[4][4], Ql[4][4];

    if (nblk > 0) {
        load_stage(0);
        asm volatile("cp.async.wait_group 1;" ::: "memory");
        __syncthreads();
#pragma unroll
        for (int kk = 0; kk < 4; kk++) {
            uint32_t off = (uint32_t)((wid * 16 + (lane & 15)) * 144
                                      + (kk * 16 + ((lane >> 4) << 3)) * 2);
            ldm_x4(Qh[kk], sbase + off);
            ldm_x4(Ql[kk], sbase + 9216 + off);
        }
    } else {
        asm volatile("cp.async.wait_group 0;" ::: "memory");
    }

    for (int i = 0; i < nblk; i++) {
        __syncthreads();
        if (i + 1 < nblk) {
            load_stage(i + 1);
            asm volatile("cp.async.wait_group 1;" ::: "memory");
        } else {
            asm volatile("cp.async.wait_group 0;" ::: "memory");
        }
        __syncthreads();

        int j0 = (i < nPast) ? (i << 6) : (P_ + ((i - nPast) << 6));
        uint32_t SB = sbase + 18432 + (i & 1) * 36864;

        float S[8][4];
#pragma unroll
        for (int nf = 0; nf < 8; nf++)
#pragma unroll
            for (int q = 0; q < 4; q++) S[nf][q] = 0.f;
#pragma unroll
        for (int nf = 0; nf < 8; nf++) {
            uint32_t kfh[4][2], kfl[4][2];
#pragma unroll
            for (int kk = 0; kk < 4; kk++) {
                uint32_t off = (uint32_t)((nf * 8 + (lane & 7)) * 144
                                          + (kk * 16 + (((lane >> 3) & 1) << 3)) * 2);
                ldm_x2(kfh[kk], SB + off);
                ldm_x2(kfl[kk], SB + 9216 + off);
            }
#pragma unroll
            for (int kk = 0; kk < 4; kk++) {
                mma16816(S[nf], Qh[kk], kfh[kk]);
                mma16816(S[nf], Qh[kk], kfl[kk]);
                mma16816(S[nf], Ql[kk], kfh[kk]);
            }
        }

#pragma unroll
        for (int nf = 0; nf < 8; nf++) {
            int keyc = j0 + nf * 8 + ((lane & 3) << 1);
            if (keyc     >= Ltot) { S[nf][0] = -1e9f; S[nf][2] = -1e9f; }
            if (keyc + 1 >= Ltot) { S[nf][1] = -1e9f; S[nf][3] = -1e9f; }
        }

        float mx0 = -1e30f, mx1 = -1e30f;
#pragma unroll
        for (int nf = 0; nf < 8; nf++) {
            mx0 = fmaxf(mx0, fmaxf(S[nf][0], S[nf][1]));
            mx1 = fmaxf(mx1, fmaxf(S[nf][2], S[nf][3]));
        }
        mx0 = fmaxf(mx0, __shfl_xor_sync(0xffffffffu, mx0, 1));
        mx0 = fmaxf(mx0, __shfl_xor_sync(0xffffffffu, mx0, 2));
        mx1 = fmaxf(mx1, __shfl_xor_sync(0xffffffffu, mx1, 1));
        mx1 = fmaxf(mx1, __shfl_xor_sync(0xffffffffu, mx1, 2));
        float nm0 = fmaxf(m0, mx0), nm1 = fmaxf(m1, mx1);
        float a0 = ex2f(m0 - nm0), a1 = ex2f(m1 - nm1);
        m0 = nm0; m1 = nm1;
        float rs0 = 0.f, rs1 = 0.f;
#pragma unroll
        for (int nf = 0; nf < 8; nf++) {
            S[nf][0] = ex2f(S[nf][0] - nm0);
            S[nf][1] = ex2f(S[nf][1] - nm0);
            S[nf][2] = ex2f(S[nf][2] - nm1);
            S[nf][3] = ex2f(S[nf][3] - nm1);
            rs0 += S[nf][0] + S[nf][1];
            rs1 += S[nf][2] + S[nf][3];
        }
        rs0 += __shfl_xor_sync(0xffffffffu, rs0, 1);
        rs0 += __shfl_xor_sync(0xffffffffu, rs0, 2);
        rs1 += __shfl_xor_sync(0xffffffffu, rs1, 1);
        rs1 += __shfl_xor_sync(0xffffffffu, rs1, 2);
        l0 = l0 * a0 + rs0;
        l1 = l1 * a1 + rs1;
#pragma unroll
        for (int nf = 0; nf < 8; nf++) {
            O[nf][0] *= a0; O[nf][1] *= a0;
            O[nf][2] *= a1; O[nf][3] *= a1;
        }

        uint32_t Ph[4][4], Pl[4][4];
#pragma unroll
        for (int kk = 0; kk < 4; kk++) {
            float p0 = S[2*kk][0],   p1 = S[2*kk][1],   p2 = S[2*kk][2],   p3 = S[2*kk][3];
            float q0 = S[2*kk+1][0], q1 = S[2*kk+1][1], q2 = S[2*kk+1][2], q3 = S[2*kk+1][3];
            uint32_t u;
            u = packbf(p0, p1); Ph[kk][0] = u; Pl[kk][0] = packbf(p0 - bflo(u), p1 - bfhi(u));
            u = packbf(p2, p3); Ph[kk][1] = u; Pl[kk][1] = packbf(p2 - bflo(u), p3 - bfhi(u));
            u = packbf(q0, q1); Ph[kk][2] = u; Pl[kk][2] = packbf(q0 - bflo(u), q1 - bfhi(u));
            u = packbf(q2, q3); Ph[kk][3] = u; Pl[kk][3] = packbf(q2 - bflo(u), q3 - bfhi(u));
        }

#pragma unroll
        for (int nf = 0; nf < 8; nf++) {
            uint32_t vfh[4][2], vfl[4][2];
#pragma unroll
            for (int kk = 0; kk < 4; kk++) {
                uint32_t off = (uint32_t)((kk * 16 + (lane & 15)) * 144 + nf * 16);
                ldm_x2t(vfh[kk], SB + 18432 + off);
                ldm_x2t(vfl[kk], SB + 27648 + off);
            }
#pragma unroll
            for (int kk = 0; kk < 4; kk++) {
                mma16816(O[nf], Ph[kk], vfh[kk]);
                mma16816(O[nf], Ph[kk], vfl[kk]);
                mma16816(O[nf], Pl[kk], vfh[kk]);
            }
        }
    }

    if (Z > 0) {
        float nm0 = fmaxf(m0, 0.f), nm1 = fmaxf(m1, 0.f);
        float a0 = ex2f(m0 - nm0), a1 = ex2f(m1 - nm1);
        l0 = l0 * a0 + (float)Z * ex2f(-nm0);
        l1 = l1 * a1 + (float)Z * ex2f(-nm1);
#pragma unroll
        for (int nf = 0; nf < 8; nf++) {
            O[nf][0] *= a0; O[nf][1] *= a0;
            O[nf][2] *= a1; O[nf][3] *= a1;
        }
    }

    float inv0 = 1.f / l0, inv1 = 1.f / l1;
    float* Os = (float*)smem;
    __syncthreads();
    {
        int r0 = wid * 16 + (lane >> 2);
        int cb = (lane & 3) << 1;
#pragma unroll
        for (int nf = 0; nf < 8; nf++) {
            *(float2*)&Os[r0 * 68 + nf * 8 + cb] =
                make_float2(O[nf][0] * inv0, O[nf][1] * inv0);
            *(float2*)&Os[(r0 + 8) * 68 + nf * 8 + cb] =
                make_float2(O[nf][2] * inv1, O[nf][3] * inv1);
        }
    }
    __syncthreads();
    {
        int r = tid >> 1;
        int half = (tid & 1) * 32;
        int t = t0 + r;
        size_t orow = ((size_t)b * T_ + t) * DM_ + h * DH_ + half;
        const float* Or = Os + r * 68 + half;
#pragma unroll
        for (int j = 0; j < 32; j += 4) {
            float v0 = Or[j], v1 = Or[j+1], v2 = Or[j+2], v3 = Or[j+3];
            __nv_bfloat16 h0=__float2bfloat16_rn(v0), h1=__float2bfloat16_rn(v1);
            __nv_bfloat16 h2=__float2bfloat16_rn(v2), h3=__float2bfloat16_rn(v3);
            ushort4 hv, lv;
            hv.x=__bfloat16_as_ushort(h0); hv.y=__bfloat16_as_ushort(h1);
            hv.z=__bfloat16_as_ushort(h2); hv.w=__bfloat16_as_ushort(h3);
            lv.x=__bfloat16_as_ushort(__float2bfloat16_rn(v0-__bfloat162float(h0)));
            lv.y=__bfloat16_as_ushort(__float2bfloat16_rn(v1-__bfloat162float(h1)));
            lv.z=__bfloat16_as_ushort(__float2bfloat16_rn(v2-__bfloat162float(h2)));
            lv.w=__bfloat16_as_ushort(__float2bfloat16_rn(v3-__bfloat162float(h3)));
            *(ushort4*)(g_at_hi + orow + j) = hv;
            *(ushort4*)(g_at_lo + orow + j) = lv;
        }
    }
}

// ---------------- launch ----------------
extern "C" void kernel_launch(void* const* d_in, const int* in_sizes, int n_in,
                              void* d_out, int out_size)
{
    const float* x   = (const float*)d_in[0];
    const float* rc  = (const float*)d_in[1];
    const float* rs  = (const float*)d_in[2];
    const float* pk  = (const float*)d_in[3];
    const float* pv  = (const float*)d_in[4];
    const int*   pl  = (const int*)  d_in[5];
    const int*   nc  = (const int*)  d_in[7];
    const float* Wq  = (const float*)d_in[8];
    const float* bq  = (const float*)d_in[9];
    const float* Wk  = (const float*)d_in[10];
    const float* bk  = (const float*)d_in[11];
    const float* Wv  = (const float*)d_in[12];
    const float* bv  = (const float*)d_in[13];
    const float* Wo  = (const float*)d_in[14];
    const float* bo  = (const float*)d_in[15];
    float* out = (float*)d_out;

    cudaFuncSetAttribute(mma_gemm_kernel,
                         cudaFuncAttributeMaxDynamicSharedMemorySize, SMEM_GEMM_);
    cudaFuncSetAttribute(gemm_out64_kernel,
                         cudaFuncAttributeMaxDynamicSharedMemorySize, SMEM_OUT_);
    cudaFuncSetAttribute(attn_mma_kernel,
                         cudaFuncAttributeMaxDynamicSharedMemorySize, SMEM_ATTN_);

    fused_prep_kernel<<<PREP_TOTAL_BLKS_, 256>>>(x, Wq, Wk, Wv, Wo, pk, pv, pl);
    mma_gemm_kernel<<<dim3(8, 32, 3), 256, SMEM_GEMM_>>>(rc, rs, bq, bk, bv, nc);
    attn_mma_kernel<<<dim3(T_/64, H_, B_), 128, SMEM_ATTN_>>>(pl, nc);
    gemm_out64_kernel<<<512, 256, SMEM_OUT_>>>(bo, out, nc);
}